// round 12
// baseline (speedup 1.0000x reference)
#include <cuda_runtime.h>
#include <cuda_fp16.h>
#include <stdint.h>

// Problem constants
#define NMAX 20000
#define NPAD 20096
#define EMAX 160000
#define GMAX 64
#define DIN  36
#define KP1  64
#define HID1 2048
#define HID2 1024

// ---------------- scratch (device globals, no runtime alloc) ----------------
__device__ float d_dinv[NMAX];
__device__ int   d_cnt[NMAX];
__device__ int   d_off[NMAX + 1];
__device__ int   d_cur[NMAX];
__device__ int   d_bsum[32];
__device__ int   d_ssrc[EMAX];
__device__ __half d_aggxh[(size_t)NPAD * KP1];   // rows >= n stay zero
__device__ __half d_w1t[(size_t)HID1 * KP1];
__device__ __half d_h1h[(size_t)NPAD * HID1];    // rows >= n stay zero
__device__ __half d_w2t[(size_t)HID2 * HID1];
__device__ __half d_yh[(size_t)NPAD * HID2];     // padded: guard-free epilogue
__device__ __half d_x2h[(size_t)NMAX * HID2];
__device__ __half d_hw1h[(size_t)1024 * 1024];   // fp16 head weights
__device__ __half d_hw2h[(size_t)1024 * 512];
__device__ float d_pooled[GMAX * HID2];
__device__ float d_hh1[GMAX * 1024];
__device__ float d_hh2[GMAX * 512];

// ---------------- PTX helpers (base ISA) ------------------------------------
__device__ __forceinline__ uint32_t smem_to_u32(const void* p) {
    uint32_t a;
    asm("{ .reg .u64 t; cvta.to.shared.u64 t, %1; cvt.u32.u64 %0, t; }" : "=r"(a) : "l"(p));
    return a;
}

#define CP_ASYNC16(dst, src) \
    asm volatile("cp.async.cg.shared.global [%0], [%1], 16;" \
        :: "r"(dst), "l"(src) : "memory")
#define CP_COMMIT()  asm volatile("cp.async.commit_group;" ::: "memory")
#define CP_WAIT0()   asm volatile("cp.async.wait_group 0;" ::: "memory")

#define LDM_X4(r0, r1, r2, r3, addr) \
    asm volatile("ldmatrix.sync.aligned.m8n8.x4.shared.b16 {%0,%1,%2,%3}, [%4];" \
        : "=r"(r0), "=r"(r1), "=r"(r2), "=r"(r3) : "r"(addr))

#define MMA_FP16(c, a, b0v, b1v) \
    asm volatile("mma.sync.aligned.m16n8k16.row.col.f32.f16.f16.f32 " \
        "{%0,%1,%2,%3},{%4,%5,%6,%7},{%8,%9},{%0,%1,%2,%3};" \
        : "+f"((c)[0]), "+f"((c)[1]), "+f"((c)[2]), "+f"((c)[3]) \
        : "r"((a)[0]), "r"((a)[1]), "r"((a)[2]), "r"((a)[3]), "r"(b0v), "r"(b1v))

// ---------------- CSR build ----------------
__global__ void k_count(const int* __restrict__ dst, int E) {
    int e = blockIdx.x * blockDim.x + threadIdx.x;
    if (e < E) atomicAdd(&d_cnt[dst[e]], 1);
}

__global__ void k_scan1(int n) {
    __shared__ int wsum[32];
    int tid = threadIdx.x, lane = tid & 31, wrp = tid >> 5;
    int i = blockIdx.x * 1024 + tid;
    int v = (i < n) ? d_cnt[i] : 0;
    int x = v;
#pragma unroll
    for (int s = 1; s < 32; s <<= 1) {
        int t = __shfl_up_sync(0xFFFFFFFF, x, s);
        if (lane >= s) x += t;
    }
    if (lane == 31) wsum[wrp] = x;
    __syncthreads();
    if (wrp == 0) {
        int w = wsum[lane];
#pragma unroll
        for (int s = 1; s < 32; s <<= 1) {
            int t = __shfl_up_sync(0xFFFFFFFF, w, s);
            if (lane >= s) w += t;
        }
        wsum[lane] = w;
    }
    __syncthreads();
    int inc = x + (wrp > 0 ? wsum[wrp - 1] : 0);
    if (i < n) d_off[i] = inc - v;
    if (tid == 1023) d_bsum[blockIdx.x] = inc;
}

__global__ void k_scan2(int nblk, int n) {
    int lane = threadIdx.x;
    int v = (lane < nblk) ? d_bsum[lane] : 0;
    int x = v;
#pragma unroll
    for (int s = 1; s < 32; s <<= 1) {
        int t = __shfl_up_sync(0xFFFFFFFF, x, s);
        if (lane >= s) x += t;
    }
    if (lane < nblk) d_bsum[lane] = x - v;
    if (lane == 31) d_off[n] = x;
}

// stage 3: add block base; emit off, cur, dinv; SELF-CLEAN cnt for next replay
__global__ void k_scan3(int n) {
    int i = blockIdx.x * 1024 + threadIdx.x;
    if (i >= n) return;
    int o = d_off[i] + d_bsum[blockIdx.x];
    int c = d_cnt[i];
    d_cnt[i] = 0;                 // restore zero state (replay-deterministic)
    d_off[i] = o;
    d_cur[i] = o;
    d_dinv[i] = rsqrtf((float)(c + 1));
}

__global__ void k_scatter(const int* __restrict__ src, const int* __restrict__ dst, int E) {
    int e = blockIdx.x * blockDim.x + threadIdx.x;
    if (e < E) {
        int d = dst[e];
        int p = atomicAdd(&d_cur[d], 1);
        d_ssrc[p] = src[e];
    }
}

// ---------------- layer-1 aggregation -> fp16 -------------------------------
__global__ void k_agg1(const int* __restrict__ ids, const float* __restrict__ feats,
                       const float* __restrict__ emb, int n) {
    int w = (blockIdx.x * blockDim.x + threadIdx.x) >> 5;
    int lane = threadIdx.x & 31;
    if (w >= n) return;
    int i = w;
    float di = d_dinv[i];
    float a0 = di * emb[(size_t)ids[i] * 32 + lane];
    float a1 = (lane < 4) ? di * feats[(size_t)i * 4 + lane] : 0.f;
    int e0 = d_off[i], e1 = d_off[i + 1];
    for (int e = e0; e < e1; ++e) {
        int s = d_ssrc[e];
        float c = d_dinv[s];
        a0 += c * emb[(size_t)ids[s] * 32 + lane];
        if (lane < 4) a1 += c * feats[(size_t)s * 4 + lane];
    }
    d_aggxh[(size_t)i * KP1 + lane] = __float2half_rn(di * a0);
    if (lane < 4) d_aggxh[(size_t)i * KP1 + 32 + lane] = __float2half_rn(di * a1);
}

// ---------------- prep weights ----------------------------------------------
__global__ void k_prepW1(const float* __restrict__ W1) {
    int idx = blockIdx.x * 256 + threadIdx.x;
    int n = idx & (HID1 - 1);
    int k = idx >> 11;
    d_w1t[(size_t)n * KP1 + k] = __float2half_rn(W1[(size_t)k * HID1 + n]);
}

__global__ void k_prepB(const float* __restrict__ W2) {
    __shared__ float t[32][33];
    int nt = blockIdx.x * 32, kt = blockIdx.y * 32;
    int x = threadIdx.x, y = threadIdx.y;
#pragma unroll
    for (int j = 0; j < 4; ++j)
        t[y + j * 8][x] = W2[(size_t)(kt + y + j * 8) * HID2 + nt + x];
    __syncthreads();
#pragma unroll
    for (int j = 0; j < 4; ++j) {
        float v = t[x][y + j * 8];
        d_w2t[(size_t)(nt + y + j * 8) * HID1 + kt + x] = __float2half_rn(v);
    }
}

__global__ void k_prepHW1(const float* __restrict__ W) {
    int idx = blockIdx.x * 256 + threadIdx.x;   // 1M elems
    d_hw1h[idx] = __float2half_rn(W[idx]);
}
__global__ void k_prepHW2(const float* __restrict__ W) {
    int idx = blockIdx.x * 256 + threadIdx.x;   // 512K elems
    d_hw2h[idx] = __float2half_rn(W[idx]);
}

// ---------------- GEMM1 via mma.sync fp16 (guard-free: NPAD rows) ----------
#define G1_ROWB 144
#define G1_MAT  (128 * G1_ROWB)

__global__ void __launch_bounds__(256) k_gemm1_mma(const float* __restrict__ bias) {
    __shared__ char smem[2 * G1_MAT];
    uint32_t sb = smem_to_u32(smem);
    const int tid = threadIdx.x;
    const int lane = tid & 31, wid = tid >> 5;
    const int wm = wid >> 2, wn = wid & 3;
    const int bn = blockIdx.x * 128;
    const int bm = blockIdx.y * 128;

#pragma unroll
    for (int i = 0; i < 4; ++i) {
        int idx = tid + i * 256;
        int row = idx >> 3, u = idx & 7;
        uint32_t so = (uint32_t)(row * G1_ROWB + u * 16);
        CP_ASYNC16(sb + so, (const char*)(d_aggxh + (size_t)(bm + row) * KP1 + u * 8));
        CP_ASYNC16(sb + G1_MAT + so,
                   (const char*)(d_w1t + (size_t)(bn + row) * KP1 + u * 8));
    }
    CP_COMMIT();

    float acc[4][4][4];
#pragma unroll
    for (int i = 0; i < 4; ++i)
#pragma unroll
        for (int j = 0; j < 4; ++j)
#pragma unroll
            for (int q = 0; q < 4; ++q) acc[i][j][q] = 0.f;

    CP_WAIT0();
    __syncthreads();

    const int lr = lane & 7;
    const int lm = lane >> 3;

    uint32_t bf[4][8];
#pragma unroll
    for (int nt = 0; nt < 4; ++nt) {
        uint32_t baddr = sb + G1_MAT +
            (uint32_t)((wn * 32 + nt * 8 + lr) * G1_ROWB + lm * 16);
        LDM_X4(bf[nt][0], bf[nt][1], bf[nt][2], bf[nt][3], baddr);
        LDM_X4(bf[nt][4], bf[nt][5], bf[nt][6], bf[nt][7], baddr + 64);
    }

#pragma unroll
    for (int ks = 0; ks < 4; ++ks) {
        uint32_t af[4][4];
#pragma unroll
        for (int mt = 0; mt < 4; ++mt) {
            uint32_t aaddr = sb +
                (uint32_t)((wm * 64 + mt * 16 + (lm & 1) * 8 + lr) * G1_ROWB +
                           ks * 32 + (lm >> 1) * 16);
            LDM_X4(af[mt][0], af[mt][1], af[mt][2], af[mt][3], aaddr);
        }
#pragma unroll
        for (int mt = 0; mt < 4; ++mt)
#pragma unroll
            for (int nt = 0; nt < 4; ++nt)
                MMA_FP16(acc[mt][nt], af[mt], bf[nt][2 * ks], bf[nt][2 * ks + 1]);
    }

    int r0 = lane >> 2;
    int c0 = (lane & 3) * 2;
#pragma unroll
    for (int nt = 0; nt < 4; ++nt) {
        int gcol = bn + wn * 32 + nt * 8 + c0;
        float b0 = bias[gcol], b1 = bias[gcol + 1];
#pragma unroll
        for (int mt = 0; mt < 4; ++mt) {
            int grow = bm + wm * 64 + mt * 16 + r0;
            *(__half2*)(d_h1h + (size_t)grow * HID1 + gcol) =
                __floats2half2_rn(fmaxf(acc[mt][nt][0] + b0, 0.f),
                                  fmaxf(acc[mt][nt][1] + b1, 0.f));
            *(__half2*)(d_h1h + (size_t)(grow + 8) * HID1 + gcol) =
                __floats2half2_rn(fmaxf(acc[mt][nt][2] + b0, 0.f),
                                  fmaxf(acc[mt][nt][3] + b1, 0.f));
        }
    }
}

// ---------------- GEMM2: block 128x64, warp 32x32, BK=32, guard-free --------
#define G2_ROWB   80
#define G2_AMAT   (128 * G2_ROWB)
#define G2_BMAT   (64 * G2_ROWB)
#define G2_BUF    (G2_AMAT + G2_BMAT)
#define G2_SMEM   (2 * G2_BUF)

__global__ void __launch_bounds__(256, 3) k_gemm2_mma() {
    extern __shared__ char smem[];
    uint32_t sb = smem_to_u32(smem);
    const int tid = threadIdx.x;
    const int lane = tid & 31, wid = tid >> 5;
    const int wm = wid >> 1, wn = wid & 1;
    const int bn = blockIdx.x * 64;
    const int bm = blockIdx.y * 128;

    const int NCHUNK = HID1 / 32;   // 64

    auto fill = [&](int buf, int kt) {
        uint32_t base = sb + buf * G2_BUF;
#pragma unroll
        for (int i = 0; i < 2; ++i) {
            int idx = tid + i * 256;
            int row = idx >> 2;
            int u = idx & 3;
            uint32_t so = (uint32_t)(row * G2_ROWB + u * 16);
            CP_ASYNC16(base + so, (const char*)(d_h1h + (size_t)(bm + row) * HID1 + kt + u * 8));
        }
        {
            int row = tid >> 2;
            int u = tid & 3;
            uint32_t so = (uint32_t)(row * G2_ROWB + u * 16);
            CP_ASYNC16(base + G2_AMAT + so,
                       (const char*)(d_w2t + (size_t)(bn + row) * HID1 + kt + u * 8));
        }
    };

    float acc[2][4][4];
#pragma unroll
    for (int i = 0; i < 2; ++i)
#pragma unroll
        for (int j = 0; j < 4; ++j)
#pragma unroll
            for (int q = 0; q < 4; ++q) acc[i][j][q] = 0.f;

    fill(0, 0);
    CP_COMMIT();
    CP_WAIT0();
    __syncthreads();

    const int lr = lane & 7;
    const int lm = lane >> 3;

    for (int c = 0; c < NCHUNK; ++c) {
        if (c + 1 < NCHUNK) {
            fill((c + 1) & 1, (c + 1) * 32);
            CP_COMMIT();
        }
        uint32_t base = sb + (c & 1) * G2_BUF;

        uint32_t bf[4][4];
#pragma unroll
        for (int nt = 0; nt < 4; ++nt) {
            uint32_t baddr = base + G2_AMAT +
                (uint32_t)((wn * 32 + nt * 8 + lr) * G2_ROWB + lm * 16);
            LDM_X4(bf[nt][0], bf[nt][1], bf[nt][2], bf[nt][3], baddr);
        }

#pragma unroll
        for (int ks = 0; ks < 2; ++ks) {
            uint32_t af[2][4];
#pragma unroll
            for (int mt = 0; mt < 2; ++mt) {
                uint32_t aaddr = base +
                    (uint32_t)((wm * 32 + mt * 16 + (lm & 1) * 8 + lr) * G2_ROWB +
                               ks * 32 + (lm >> 1) * 16);
                LDM_X4(af[mt][0], af[mt][1], af[mt][2], af[mt][3], aaddr);
            }
#pragma unroll
            for (int mt = 0; mt < 2; ++mt)
#pragma unroll
                for (int nt = 0; nt < 4; ++nt)
                    MMA_FP16(acc[mt][nt], af[mt], bf[nt][2 * ks], bf[nt][2 * ks + 1]);
        }
        CP_WAIT0();
        __syncthreads();
    }

    int r0 = lane >> 2;
    int c0 = (lane & 3) * 2;
#pragma unroll
    for (int mt = 0; mt < 2; ++mt) {
#pragma unroll
        for (int nt = 0; nt < 4; ++nt) {
            int grow = bm + wm * 32 + mt * 16 + r0;
            int gcol = bn + wn * 32 + nt * 8 + c0;
            *(__half2*)(d_yh + (size_t)grow * HID2 + gcol) =
                __floats2half2_rn(acc[mt][nt][0], acc[mt][nt][1]);
            *(__half2*)(d_yh + (size_t)(grow + 8) * HID2 + gcol) =
                __floats2half2_rn(acc[mt][nt][2], acc[mt][nt][3]);
        }
    }
}

// ---------------- layer-2 aggregation + bias + relu (2-way unrolled) --------
__global__ void k_agg2(const float* __restrict__ b2, int n) {
    int i = blockIdx.x;
    int tid = threadIdx.x;
    float di = d_dinv[i];
    const uint2* Y = (const uint2*)d_yh;
    uint2 raw = Y[(size_t)i * 256 + tid];
    float2 p0 = __half22float2(*(__half2*)&raw.x);
    float2 p1 = __half22float2(*(__half2*)&raw.y);
    float c0 = di * di;
    float4 acc = make_float4(p0.x * c0, p0.y * c0, p1.x * c0, p1.y * c0);
    int e0 = d_off[i], e1 = d_off[i + 1];
    int e = e0;
    for (; e + 1 < e1; e += 2) {
        int s0 = d_ssrc[e], s1 = d_ssrc[e + 1];
        float ca = di * d_dinv[s0];
        float cb = di * d_dinv[s1];
        uint2 ua = Y[(size_t)s0 * 256 + tid];
        uint2 ub = Y[(size_t)s1 * 256 + tid];
        float2 qa0 = __half22float2(*(__half2*)&ua.x);
        float2 qa1 = __half22float2(*(__half2*)&ua.y);
        float2 qb0 = __half22float2(*(__half2*)&ub.x);
        float2 qb1 = __half22float2(*(__half2*)&ub.y);
        acc.x += ca * qa0.x + cb * qb0.x;
        acc.y += ca * qa0.y + cb * qb0.y;
        acc.z += ca * qa1.x + cb * qb1.x;
        acc.w += ca * qa1.y + cb * qb1.y;
    }
    if (e < e1) {
        int s = d_ssrc[e];
        float c = di * d_dinv[s];
        uint2 u = Y[(size_t)s * 256 + tid];
        float2 q0 = __half22float2(*(__half2*)&u.x);
        float2 q1 = __half22float2(*(__half2*)&u.y);
        acc.x += c * q0.x;
        acc.y += c * q0.y;
        acc.z += c * q1.x;
        acc.w += c * q1.y;
    }
    float4 bb = ((const float4*)b2)[tid];
    uint2 out;
    *(__half2*)&out.x = __floats2half2_rn(fmaxf(acc.x + bb.x, 0.f),
                                          fmaxf(acc.y + bb.y, 0.f));
    *(__half2*)&out.y = __floats2half2_rn(fmaxf(acc.z + bb.z, 0.f),
                                          fmaxf(acc.w + bb.w, 0.f));
    ((uint2*)d_x2h)[(size_t)i * 256 + tid] = out;
}

// ---------------- mean pool per graph ----------------------------------------
__global__ void k_pool(const int* __restrict__ batch, int n) {
    int g = blockIdx.x;
    int tid = threadIdx.x;
    int lo = 0, hi = n;
    while (lo < hi) { int m = (lo + hi) >> 1; if (batch[m] < g) lo = m + 1; else hi = m; }
    int s0 = lo;
    hi = n;
    while (lo < hi) { int m = (lo + hi) >> 1; if (batch[m] <= g) lo = m + 1; else hi = m; }
    int s1 = lo;
    float4 acc = make_float4(0.f, 0.f, 0.f, 0.f);
    const uint2* X = (const uint2*)d_x2h;
    for (int i = s0; i < s1; ++i) {
        uint2 u = X[(size_t)i * 256 + tid];
        float2 q0 = __half22float2(*(__half2*)&u.x);
        float2 q1 = __half22float2(*(__half2*)&u.y);
        acc.x += q0.x; acc.y += q0.y; acc.z += q1.x; acc.w += q1.y;
    }
    int c = s1 - s0;
    float inv = 1.f / (float)(c > 0 ? c : 1);
    ((float4*)d_pooled)[g * 256 + tid] =
        make_float4(acc.x * inv, acc.y * inv, acc.z * inv, acc.w * inv);
}

// ---------------- small MLP head (fp16 weights, 2 cols/thread) ---------------
__global__ void k_mlp1(const float* __restrict__ bias) {
    __shared__ float sp[1024];
    const int Kd = 1024, Nd = 1024;
    int g = blockIdx.x, cq = blockIdx.y, tid = threadIdx.x;
    for (int k = tid; k < Kd; k += 256) sp[k] = d_pooled[(size_t)g * Kd + k];
    __syncthreads();
    int c = cq * 512 + tid * 2;
    float a0 = bias[c], a1 = bias[c + 1];
#pragma unroll 4
    for (int k = 0; k < Kd; ++k) {
        float pk = sp[k];
        float2 w = __half22float2(*(const __half2*)(d_hw1h + (size_t)k * Nd + c));
        a0 += pk * w.x;
        a1 += pk * w.y;
    }
    d_hh1[(size_t)g * Nd + c] = fmaxf(a0, 0.f);
    d_hh1[(size_t)g * Nd + c + 1] = fmaxf(a1, 0.f);
}

__global__ void k_mlp2(const float* __restrict__ bias) {
    __shared__ float sp[1024];
    const int Kd = 1024, Nd = 512;
    int g = blockIdx.x, tid = threadIdx.x;
    for (int k = tid; k < Kd; k += 256) sp[k] = d_hh1[(size_t)g * Kd + k];
    __syncthreads();
    int c = tid * 2;
    float a0 = bias[c], a1 = bias[c + 1];
#pragma unroll 4
    for (int k = 0; k < Kd; ++k) {
        float pk = sp[k];
        float2 w = __half22float2(*(const __half2*)(d_hw2h + (size_t)k * Nd + c));
        a0 += pk * w.x;
        a1 += pk * w.y;
    }
    d_hh2[(size_t)g * Nd + c] = fmaxf(a0, 0.f);
    d_hh2[(size_t)g * Nd + c + 1] = fmaxf(a1, 0.f);
}

// one warp per output element, shuffle reduce
__global__ void k_out(const float* __restrict__ oW, const float* __restrict__ ob,
                      float* __restrict__ out, int G) {
    int w = (blockIdx.x * blockDim.x + threadIdx.x) >> 5;
    int lane = threadIdx.x & 31;
    if (w >= G * 2) return;
    int g = w >> 1, c = w & 1;
    float acc = 0.f;
    for (int k = lane; k < 512; k += 32)
        acc += d_hh2[g * 512 + k] * oW[k * 2 + c];
#pragma unroll
    for (int s = 16; s; s >>= 1) acc += __shfl_down_sync(0xFFFFFFFF, acc, s);
    if (lane == 0) out[w] = acc + ob[c];
}

// ---------------- launch ------------------------------------------------------
extern "C" void kernel_launch(void* const* d_in, const int* in_sizes, int n_in,
                              void* d_out, int out_size) {
    const int*   ids   = (const int*)  d_in[0];
    const float* feats = (const float*)d_in[1];
    const int*   eidx  = (const int*)  d_in[2];
    const int*   batch = (const int*)  d_in[3];
    const float* emb   = (const float*)d_in[4];
    const float* W1    = (const float*)d_in[5];
    const float* b1    = (const float*)d_in[6];
    const float* W2    = (const float*)d_in[7];
    const float* b2    = (const float*)d_in[8];
    const float* hW1   = (const float*)d_in[9];
    const float* hb1   = (const float*)d_in[10];
    const float* hW2   = (const float*)d_in[11];
    const float* hb2   = (const float*)d_in[12];
    const float* oW    = (const float*)d_in[13];
    const float* ob    = (const float*)d_in[14];

    int n = in_sizes[0];
    int E = in_sizes[2] / 2;
    int G = out_size / 2;

    const int* src = eidx;
    const int* dst = eidx + E;

    static bool attr_done = false;
    if (!attr_done) {
        cudaFuncSetAttribute(k_gemm2_mma, cudaFuncAttributeMaxDynamicSharedMemorySize,
                             G2_SMEM);
        attr_done = true;
    }

    int nblk = (n + 1023) / 1024;

    k_count<<<(E + 255) / 256, 256>>>(dst, E);
    k_scan1<<<nblk, 1024>>>(n);
    k_scan2<<<1, 32>>>(nblk, n);
    k_scan3<<<nblk, 1024>>>(n);
    k_scatter<<<(E + 255) / 256, 256>>>(src, dst, E);

    k_prepW1<<<(DIN * HID1) / 256, 256>>>(W1);
    dim3 gp(HID2 / 32, HID1 / 32);
    k_prepB<<<gp, dim3(32, 8)>>>(W2);
    k_prepHW1<<<(1024 * 1024) / 256, 256>>>(hW1);
    k_prepHW2<<<(1024 * 512) / 256, 256>>>(hW2);

    k_agg1<<<(n + 7) / 8, 256>>>(ids, feats, emb, n);

    dim3 g1(HID1 / 128, (n + 127) / 128);
    k_gemm1_mma<<<g1, 256>>>(b1);

    dim3 g2(HID2 / 64, (n + 127) / 128);
    k_gemm2_mma<<<g2, 256, G2_SMEM>>>();

    k_agg2<<<n, 256>>>(b2, n);

    k_pool<<<G, 256>>>(batch, n);

    k_mlp1<<<dim3(G, 2), 256>>>(hb1);
    k_mlp2<<<G, 256>>>(hb2);

    k_out<<<16, 256>>>(oW, ob, (float*)d_out, G);
}

// round 13
// speedup vs baseline: 1.1032x; 1.1032x over previous
#include <cuda_runtime.h>
#include <cuda_fp16.h>
#include <stdint.h>

// Problem constants
#define NMAX 20000
#define NPAD 20096
#define EMAX 160000
#define GMAX 64
#define DIN  36
#define KP1  64
#define HID1 2048
#define HID2 1024

// ---------------- scratch (device globals, no runtime alloc) ----------------
__device__ float d_dinv[NMAX];
__device__ int   d_cnt[NMAX];
__device__ int   d_off[NMAX + 1];
__device__ int   d_cur[NMAX];
__device__ int   d_bsum[32];
__device__ int   d_ssrc[EMAX];
__device__ __half d_aggxh[(size_t)NPAD * KP1];   // rows >= n stay zero
__device__ __half d_w1t[(size_t)HID1 * KP1];
__device__ __half d_h1h[(size_t)NPAD * HID1];    // rows >= n stay zero
__device__ __half d_w2t[(size_t)HID2 * HID1];
__device__ __half d_yh[(size_t)NPAD * HID2];     // padded: guard-free epilogue
__device__ __half d_x2h[(size_t)NMAX * HID2];
__device__ float d_pooled[GMAX * HID2];
__device__ float d_hh1[GMAX * 1024];
__device__ float d_hh2[GMAX * 512];

// ---------------- PTX helpers (base ISA) ------------------------------------
__device__ __forceinline__ uint32_t smem_to_u32(const void* p) {
    uint32_t a;
    asm("{ .reg .u64 t; cvta.to.shared.u64 t, %1; cvt.u32.u64 %0, t; }" : "=r"(a) : "l"(p));
    return a;
}

#define CP_ASYNC16(dst, src) \
    asm volatile("cp.async.cg.shared.global [%0], [%1], 16;" \
        :: "r"(dst), "l"(src) : "memory")
#define CP_COMMIT()  asm volatile("cp.async.commit_group;" ::: "memory")
#define CP_WAIT0()   asm volatile("cp.async.wait_group 0;" ::: "memory")

#define LDM_X4(r0, r1, r2, r3, addr) \
    asm volatile("ldmatrix.sync.aligned.m8n8.x4.shared.b16 {%0,%1,%2,%3}, [%4];" \
        : "=r"(r0), "=r"(r1), "=r"(r2), "=r"(r3) : "r"(addr))

#define MMA_FP16(c, a, b0v, b1v) \
    asm volatile("mma.sync.aligned.m16n8k16.row.col.f32.f16.f16.f32 " \
        "{%0,%1,%2,%3},{%4,%5,%6,%7},{%8,%9},{%0,%1,%2,%3};" \
        : "+f"((c)[0]), "+f"((c)[1]), "+f"((c)[2]), "+f"((c)[3]) \
        : "r"((a)[0]), "r"((a)[1]), "r"((a)[2]), "r"((a)[3]), "r"(b0v), "r"(b1v))

// ---------------- CSR build ----------------
__global__ void k_count(const int* __restrict__ dst, int E) {
    int e = blockIdx.x * blockDim.x + threadIdx.x;
    if (e < E) atomicAdd(&d_cnt[dst[e]], 1);
}

__global__ void k_scan1(int n) {
    __shared__ int wsum[32];
    int tid = threadIdx.x, lane = tid & 31, wrp = tid >> 5;
    int i = blockIdx.x * 1024 + tid;
    int v = (i < n) ? d_cnt[i] : 0;
    int x = v;
#pragma unroll
    for (int s = 1; s < 32; s <<= 1) {
        int t = __shfl_up_sync(0xFFFFFFFF, x, s);
        if (lane >= s) x += t;
    }
    if (lane == 31) wsum[wrp] = x;
    __syncthreads();
    if (wrp == 0) {
        int w = wsum[lane];
#pragma unroll
        for (int s = 1; s < 32; s <<= 1) {
            int t = __shfl_up_sync(0xFFFFFFFF, w, s);
            if (lane >= s) w += t;
        }
        wsum[lane] = w;
    }
    __syncthreads();
    int inc = x + (wrp > 0 ? wsum[wrp - 1] : 0);
    if (i < n) d_off[i] = inc - v;
    if (tid == 1023) d_bsum[blockIdx.x] = inc;
}

__global__ void k_scan2(int nblk, int n) {
    int lane = threadIdx.x;
    int v = (lane < nblk) ? d_bsum[lane] : 0;
    int x = v;
#pragma unroll
    for (int s = 1; s < 32; s <<= 1) {
        int t = __shfl_up_sync(0xFFFFFFFF, x, s);
        if (lane >= s) x += t;
    }
    if (lane < nblk) d_bsum[lane] = x - v;
    if (lane == 31) d_off[n] = x;
}

// stage 3: add block base; emit off, cur, dinv; SELF-CLEAN cnt for next replay
__global__ void k_scan3(int n) {
    int i = blockIdx.x * 1024 + threadIdx.x;
    if (i >= n) return;
    int o = d_off[i] + d_bsum[blockIdx.x];
    int c = d_cnt[i];
    d_cnt[i] = 0;
    d_off[i] = o;
    d_cur[i] = o;
    d_dinv[i] = rsqrtf((float)(c + 1));
}

__global__ void k_scatter(const int* __restrict__ src, const int* __restrict__ dst, int E) {
    int e = blockIdx.x * blockDim.x + threadIdx.x;
    if (e < E) {
        int d = dst[e];
        int p = atomicAdd(&d_cur[d], 1);
        d_ssrc[p] = src[e];
    }
}

// ---------------- layer-1 aggregation -> fp16 -------------------------------
__global__ void k_agg1(const int* __restrict__ ids, const float* __restrict__ feats,
                       const float* __restrict__ emb, int n) {
    int w = (blockIdx.x * blockDim.x + threadIdx.x) >> 5;
    int lane = threadIdx.x & 31;
    if (w >= n) return;
    int i = w;
    float di = d_dinv[i];
    float a0 = di * emb[(size_t)ids[i] * 32 + lane];
    float a1 = (lane < 4) ? di * feats[(size_t)i * 4 + lane] : 0.f;
    int e0 = d_off[i], e1 = d_off[i + 1];
    for (int e = e0; e < e1; ++e) {
        int s = d_ssrc[e];
        float c = d_dinv[s];
        a0 += c * emb[(size_t)ids[s] * 32 + lane];
        if (lane < 4) a1 += c * feats[(size_t)s * 4 + lane];
    }
    d_aggxh[(size_t)i * KP1 + lane] = __float2half_rn(di * a0);
    if (lane < 4) d_aggxh[(size_t)i * KP1 + 32 + lane] = __float2half_rn(di * a1);
}

// ---------------- prep weights ----------------------------------------------
__global__ void k_prepW1(const float* __restrict__ W1) {
    int idx = blockIdx.x * 256 + threadIdx.x;
    int n = idx & (HID1 - 1);
    int k = idx >> 11;
    d_w1t[(size_t)n * KP1 + k] = __float2half_rn(W1[(size_t)k * HID1 + n]);
}

__global__ void k_prepB(const float* __restrict__ W2) {
    __shared__ float t[32][33];
    int nt = blockIdx.x * 32, kt = blockIdx.y * 32;
    int x = threadIdx.x, y = threadIdx.y;
#pragma unroll
    for (int j = 0; j < 4; ++j)
        t[y + j * 8][x] = W2[(size_t)(kt + y + j * 8) * HID2 + nt + x];
    __syncthreads();
#pragma unroll
    for (int j = 0; j < 4; ++j) {
        float v = t[x][y + j * 8];
        d_w2t[(size_t)(nt + y + j * 8) * HID1 + kt + x] = __float2half_rn(v);
    }
}

// ---------------- GEMM1 via mma.sync fp16 (guard-free: NPAD rows) ----------
#define G1_ROWB 144
#define G1_MAT  (128 * G1_ROWB)

__global__ void __launch_bounds__(256) k_gemm1_mma(const float* __restrict__ bias) {
    __shared__ char smem[2 * G1_MAT];
    uint32_t sb = smem_to_u32(smem);
    const int tid = threadIdx.x;
    const int lane = tid & 31, wid = tid >> 5;
    const int wm = wid >> 2, wn = wid & 3;
    const int bn = blockIdx.x * 128;
    const int bm = blockIdx.y * 128;

#pragma unroll
    for (int i = 0; i < 4; ++i) {
        int idx = tid + i * 256;
        int row = idx >> 3, u = idx & 7;
        uint32_t so = (uint32_t)(row * G1_ROWB + u * 16);
        CP_ASYNC16(sb + so, (const char*)(d_aggxh + (size_t)(bm + row) * KP1 + u * 8));
        CP_ASYNC16(sb + G1_MAT + so,
                   (const char*)(d_w1t + (size_t)(bn + row) * KP1 + u * 8));
    }
    CP_COMMIT();

    float acc[4][4][4];
#pragma unroll
    for (int i = 0; i < 4; ++i)
#pragma unroll
        for (int j = 0; j < 4; ++j)
#pragma unroll
            for (int q = 0; q < 4; ++q) acc[i][j][q] = 0.f;

    CP_WAIT0();
    __syncthreads();

    const int lr = lane & 7;
    const int lm = lane >> 3;

    uint32_t bf[4][8];
#pragma unroll
    for (int nt = 0; nt < 4; ++nt) {
        uint32_t baddr = sb + G1_MAT +
            (uint32_t)((wn * 32 + nt * 8 + lr) * G1_ROWB + lm * 16);
        LDM_X4(bf[nt][0], bf[nt][1], bf[nt][2], bf[nt][3], baddr);
        LDM_X4(bf[nt][4], bf[nt][5], bf[nt][6], bf[nt][7], baddr + 64);
    }

#pragma unroll
    for (int ks = 0; ks < 4; ++ks) {
        uint32_t af[4][4];
#pragma unroll
        for (int mt = 0; mt < 4; ++mt) {
            uint32_t aaddr = sb +
                (uint32_t)((wm * 64 + mt * 16 + (lm & 1) * 8 + lr) * G1_ROWB +
                           ks * 32 + (lm >> 1) * 16);
            LDM_X4(af[mt][0], af[mt][1], af[mt][2], af[mt][3], aaddr);
        }
#pragma unroll
        for (int mt = 0; mt < 4; ++mt)
#pragma unroll
            for (int nt = 0; nt < 4; ++nt)
                MMA_FP16(acc[mt][nt], af[mt], bf[nt][2 * ks], bf[nt][2 * ks + 1]);
    }

    int r0 = lane >> 2;
    int c0 = (lane & 3) * 2;
#pragma unroll
    for (int nt = 0; nt < 4; ++nt) {
        int gcol = bn + wn * 32 + nt * 8 + c0;
        float b0 = bias[gcol], b1 = bias[gcol + 1];
#pragma unroll
        for (int mt = 0; mt < 4; ++mt) {
            int grow = bm + wm * 64 + mt * 16 + r0;
            *(__half2*)(d_h1h + (size_t)grow * HID1 + gcol) =
                __floats2half2_rn(fmaxf(acc[mt][nt][0] + b0, 0.f),
                                  fmaxf(acc[mt][nt][1] + b1, 0.f));
            *(__half2*)(d_h1h + (size_t)(grow + 8) * HID1 + gcol) =
                __floats2half2_rn(fmaxf(acc[mt][nt][2] + b0, 0.f),
                                  fmaxf(acc[mt][nt][3] + b1, 0.f));
        }
    }
}

// ---------------- GEMM2: block 128x64, warp 32x32, BK=64 (2 halves/sync) ----
// 8 warps = 4(m) x 2(n). Same register footprint as BK=32 version (bf reloaded
// per 32-K half) but HALF the wait+__syncthreads barriers (32 instead of 64).
// Rows padded to 144B (9x16B units -> conflict-free ldmatrix).
#define G2_ROWB   144
#define G2_AMAT   (128 * G2_ROWB)          // 18432
#define G2_BMAT   (64 * G2_ROWB)           // 9216
#define G2_BUF    (G2_AMAT + G2_BMAT)      // 27648
#define G2_SMEM   (2 * G2_BUF)             // 55296

__global__ void __launch_bounds__(256, 3) k_gemm2_mma() {
    extern __shared__ char smem[];
    uint32_t sb = smem_to_u32(smem);
    const int tid = threadIdx.x;
    const int lane = tid & 31, wid = tid >> 5;
    const int wm = wid >> 1, wn = wid & 1;       // 4(m) x 2(n)
    const int bn = blockIdx.x * 64;
    const int bm = blockIdx.y * 128;

    const int NCHUNK = HID1 / 64;   // 32

    // fill one 64-K buffer: A 1024 units, B 512 units = 6 cp.async/thread
    auto fill = [&](int buf, int kt) {
        uint32_t base = sb + buf * G2_BUF;
#pragma unroll
        for (int i = 0; i < 4; ++i) {
            int idx = tid + i * 256;        // 0..1023
            int row = idx >> 3;
            int u = idx & 7;
            uint32_t so = (uint32_t)(row * G2_ROWB + u * 16);
            CP_ASYNC16(base + so, (const char*)(d_h1h + (size_t)(bm + row) * HID1 + kt + u * 8));
        }
#pragma unroll
        for (int i = 0; i < 2; ++i) {
            int idx = tid + i * 256;        // 0..511
            int row = idx >> 3;
            int u = idx & 7;
            uint32_t so = (uint32_t)(row * G2_ROWB + u * 16);
            CP_ASYNC16(base + G2_AMAT + so,
                       (const char*)(d_w2t + (size_t)(bn + row) * HID1 + kt + u * 8));
        }
    };

    float acc[2][4][4];
#pragma unroll
    for (int i = 0; i < 2; ++i)
#pragma unroll
        for (int j = 0; j < 4; ++j)
#pragma unroll
            for (int q = 0; q < 4; ++q) acc[i][j][q] = 0.f;

    fill(0, 0);
    CP_COMMIT();
    CP_WAIT0();
    __syncthreads();

    const int lr = lane & 7;
    const int lm = lane >> 3;

    for (int c = 0; c < NCHUNK; ++c) {
        if (c + 1 < NCHUNK) {
            fill((c + 1) & 1, (c + 1) * 64);
            CP_COMMIT();
        }
        uint32_t base = sb + (c & 1) * G2_BUF;

#pragma unroll
        for (int half = 0; half < 2; ++half) {
            // B fragments for this 32-K half
            uint32_t bf[4][4];
#pragma unroll
            for (int nt = 0; nt < 4; ++nt) {
                uint32_t baddr = base + G2_AMAT +
                    (uint32_t)((wn * 32 + nt * 8 + lr) * G2_ROWB + half * 64 + lm * 16);
                LDM_X4(bf[nt][0], bf[nt][1], bf[nt][2], bf[nt][3], baddr);
            }
#pragma unroll
            for (int ks = 0; ks < 2; ++ks) {
                uint32_t af[2][4];
#pragma unroll
                for (int mt = 0; mt < 2; ++mt) {
                    uint32_t aaddr = base +
                        (uint32_t)((wm * 32 + mt * 16 + (lm & 1) * 8 + lr) * G2_ROWB +
                                   half * 64 + ks * 32 + (lm >> 1) * 16);
                    LDM_X4(af[mt][0], af[mt][1], af[mt][2], af[mt][3], aaddr);
                }
#pragma unroll
                for (int mt = 0; mt < 2; ++mt)
#pragma unroll
                    for (int nt = 0; nt < 4; ++nt)
                        MMA_FP16(acc[mt][nt], af[mt], bf[nt][2 * ks], bf[nt][2 * ks + 1]);
            }
        }
        CP_WAIT0();
        __syncthreads();
    }

    int r0 = lane >> 2;
    int c0 = (lane & 3) * 2;
#pragma unroll
    for (int mt = 0; mt < 2; ++mt) {
#pragma unroll
        for (int nt = 0; nt < 4; ++nt) {
            int grow = bm + wm * 32 + mt * 16 + r0;
            int gcol = bn + wn * 32 + nt * 8 + c0;
            *(__half2*)(d_yh + (size_t)grow * HID2 + gcol) =
                __floats2half2_rn(acc[mt][nt][0], acc[mt][nt][1]);
            *(__half2*)(d_yh + (size_t)(grow + 8) * HID2 + gcol) =
                __floats2half2_rn(acc[mt][nt][2], acc[mt][nt][3]);
        }
    }
}

// ---------------- layer-2 aggregation + bias + relu (2-way unrolled) --------
__global__ void k_agg2(const float* __restrict__ b2, int n) {
    int i = blockIdx.x;
    int tid = threadIdx.x;
    float di = d_dinv[i];
    const uint2* Y = (const uint2*)d_yh;
    uint2 raw = Y[(size_t)i * 256 + tid];
    float2 p0 = __half22float2(*(__half2*)&raw.x);
    float2 p1 = __half22float2(*(__half2*)&raw.y);
    float c0 = di * di;
    float4 acc = make_float4(p0.x * c0, p0.y * c0, p1.x * c0, p1.y * c0);
    int e0 = d_off[i], e1 = d_off[i + 1];
    int e = e0;
    for (; e + 1 < e1; e += 2) {
        int s0 = d_ssrc[e], s1 = d_ssrc[e + 1];
        float ca = di * d_dinv[s0];
        float cb = di * d_dinv[s1];
        uint2 ua = Y[(size_t)s0 * 256 + tid];
        uint2 ub = Y[(size_t)s1 * 256 + tid];
        float2 qa0 = __half22float2(*(__half2*)&ua.x);
        float2 qa1 = __half22float2(*(__half2*)&ua.y);
        float2 qb0 = __half22float2(*(__half2*)&ub.x);
        float2 qb1 = __half22float2(*(__half2*)&ub.y);
        acc.x += ca * qa0.x + cb * qb0.x;
        acc.y += ca * qa0.y + cb * qb0.y;
        acc.z += ca * qa1.x + cb * qb1.x;
        acc.w += ca * qa1.y + cb * qb1.y;
    }
    if (e < e1) {
        int s = d_ssrc[e];
        float c = di * d_dinv[s];
        uint2 u = Y[(size_t)s * 256 + tid];
        float2 q0 = __half22float2(*(__half2*)&u.x);
        float2 q1 = __half22float2(*(__half2*)&u.y);
        acc.x += c * q0.x;
        acc.y += c * q0.y;
        acc.z += c * q1.x;
        acc.w += c * q1.y;
    }
    float4 bb = ((const float4*)b2)[tid];
    uint2 out;
    *(__half2*)&out.x = __floats2half2_rn(fmaxf(acc.x + bb.x, 0.f),
                                          fmaxf(acc.y + bb.y, 0.f));
    *(__half2*)&out.y = __floats2half2_rn(fmaxf(acc.z + bb.z, 0.f),
                                          fmaxf(acc.w + bb.w, 0.f));
    ((uint2*)d_x2h)[(size_t)i * 256 + tid] = out;
}

// ---------------- mean pool per graph ----------------------------------------
__global__ void k_pool(const int* __restrict__ batch, int n) {
    int g = blockIdx.x;
    int tid = threadIdx.x;
    int lo = 0, hi = n;
    while (lo < hi) { int m = (lo + hi) >> 1; if (batch[m] < g) lo = m + 1; else hi = m; }
    int s0 = lo;
    hi = n;
    while (lo < hi) { int m = (lo + hi) >> 1; if (batch[m] <= g) lo = m + 1; else hi = m; }
    int s1 = lo;
    float4 acc = make_float4(0.f, 0.f, 0.f, 0.f);
    const uint2* X = (const uint2*)d_x2h;
    for (int i = s0; i < s1; ++i) {
        uint2 u = X[(size_t)i * 256 + tid];
        float2 q0 = __half22float2(*(__half2*)&u.x);
        float2 q1 = __half22float2(*(__half2*)&u.y);
        acc.x += q0.x; acc.y += q0.y; acc.z += q1.x; acc.w += q1.y;
    }
    int c = s1 - s0;
    float inv = 1.f / (float)(c > 0 ? c : 1);
    ((float4*)d_pooled)[g * 256 + tid] =
        make_float4(acc.x * inv, acc.y * inv, acc.z * inv, acc.w * inv);
}

// ---------------- small MLP head (fp32 weights, as in R11 best) -------------
__global__ void k_mlp1(const float* __restrict__ W, const float* __restrict__ bias) {
    __shared__ float sp[1024];
    const int Kd = 1024, Nd = 1024;
    int g = blockIdx.x, cq = blockIdx.y, tid = threadIdx.x;
    for (int k = tid; k < Kd; k += 256) sp[k] = d_pooled[(size_t)g * Kd + k];
    __syncthreads();
    int c = cq * 256 + tid;
    float acc = bias[c];
#pragma unroll 4
    for (int k = 0; k < Kd; ++k)
        acc += sp[k] * W[(size_t)k * Nd + c];
    d_hh1[(size_t)g * Nd + c] = fmaxf(acc, 0.f);
}

__global__ void k_mlp2(const float* __restrict__ W, const float* __restrict__ bias) {
    __shared__ float sp[1024];
    const int Kd = 1024, Nd = 512;
    int g = blockIdx.x, cq = blockIdx.y, tid = threadIdx.x;
    for (int k = tid; k < Kd; k += 256) sp[k] = d_hh1[(size_t)g * Kd + k];
    __syncthreads();
    int c = cq * 256 + tid;
    float acc = bias[c];
#pragma unroll 4
    for (int k = 0; k < Kd; ++k)
        acc += sp[k] * W[(size_t)k * Nd + c];
    d_hh2[(size_t)g * Nd + c] = fmaxf(acc, 0.f);
}

// one warp per output element, shuffle reduce
__global__ void k_out(const float* __restrict__ oW, const float* __restrict__ ob,
                      float* __restrict__ out, int G) {
    int w = (blockIdx.x * blockDim.x + threadIdx.x) >> 5;
    int lane = threadIdx.x & 31;
    if (w >= G * 2) return;
    int g = w >> 1, c = w & 1;
    float acc = 0.f;
    for (int k = lane; k < 512; k += 32)
        acc += d_hh2[g * 512 + k] * oW[k * 2 + c];
#pragma unroll
    for (int s = 16; s; s >>= 1) acc += __shfl_down_sync(0xFFFFFFFF, acc, s);
    if (lane == 0) out[w] = acc + ob[c];
}

// ---------------- launch ------------------------------------------------------
extern "C" void kernel_launch(void* const* d_in, const int* in_sizes, int n_in,
                              void* d_out, int out_size) {
    const int*   ids   = (const int*)  d_in[0];
    const float* feats = (const float*)d_in[1];
    const int*   eidx  = (const int*)  d_in[2];
    const int*   batch = (const int*)  d_in[3];
    const float* emb   = (const float*)d_in[4];
    const float* W1    = (const float*)d_in[5];
    const float* b1    = (const float*)d_in[6];
    const float* W2    = (const float*)d_in[7];
    const float* b2    = (const float*)d_in[8];
    const float* hW1   = (const float*)d_in[9];
    const float* hb1   = (const float*)d_in[10];
    const float* hW2   = (const float*)d_in[11];
    const float* hb2   = (const float*)d_in[12];
    const float* oW    = (const float*)d_in[13];
    const float* ob    = (const float*)d_in[14];

    int n = in_sizes[0];
    int E = in_sizes[2] / 2;
    int G = out_size / 2;

    const int* src = eidx;
    const int* dst = eidx + E;

    static bool attr_done = false;
    if (!attr_done) {
        cudaFuncSetAttribute(k_gemm2_mma, cudaFuncAttributeMaxDynamicSharedMemorySize,
                             G2_SMEM);
        attr_done = true;
    }

    int nblk = (n + 1023) / 1024;

    k_count<<<(E + 255) / 256, 256>>>(dst, E);
    k_scan1<<<nblk, 1024>>>(n);
    k_scan2<<<1, 32>>>(nblk, n);
    k_scan3<<<nblk, 1024>>>(n);
    k_scatter<<<(E + 255) / 256, 256>>>(src, dst, E);

    k_prepW1<<<(DIN * HID1) / 256, 256>>>(W1);
    dim3 gp(HID2 / 32, HID1 / 32);
    k_prepB<<<gp, dim3(32, 8)>>>(W2);

    k_agg1<<<(n + 7) / 8, 256>>>(ids, feats, emb, n);

    dim3 g1(HID1 / 128, (n + 127) / 128);
    k_gemm1_mma<<<g1, 256>>>(b1);

    dim3 g2(HID2 / 64, (n + 127) / 128);
    k_gemm2_mma<<<g2, 256, G2_SMEM>>>();

    k_agg2<<<n, 256>>>(b2, n);

    k_pool<<<G, 256>>>(batch, n);

    k_mlp1<<<dim3(G, 4), 256>>>(hW1, hb1);
    k_mlp2<<<dim3(G, 2), 256>>>(hW2, hb2);

    k_out<<<16, 256>>>(oW, ob, (float*)d_out, G);
}

// round 14
// speedup vs baseline: 1.1197x; 1.0150x over previous
#include <cuda_runtime.h>
#include <cuda_fp16.h>
#include <stdint.h>

// Problem constants
#define NMAX 20000
#define NPAD 20096
#define EMAX 160000
#define GMAX 64
#define DIN  36
#define KP1  64
#define HID1 2048
#define HID2 1024

// ---------------- scratch (device globals, no runtime alloc) ----------------
__device__ float d_dinv[NMAX];
__device__ int   d_cnt[NMAX];
__device__ int   d_off[NMAX + 1];
__device__ int   d_cur[NMAX];
__device__ int   d_bsum[32];
__device__ int   d_ssrc[EMAX];
__device__ __half d_aggxh[(size_t)NPAD * KP1];   // rows >= n stay zero
__device__ __half d_w1t[(size_t)HID1 * KP1];
__device__ __half d_h1h[(size_t)NPAD * HID1];    // rows >= n stay zero
__device__ __half d_w2t[(size_t)HID2 * HID1];
__device__ __half d_yh[(size_t)NPAD * HID2];     // padded: guard-free epilogue
__device__ __half d_x2h[(size_t)NMAX * HID2];
__device__ float d_pooled[GMAX * HID2];
__device__ float d_hh1[GMAX * 1024];

// ---------------- PTX helpers (base ISA) ------------------------------------
__device__ __forceinline__ uint32_t smem_to_u32(const void* p) {
    uint32_t a;
    asm("{ .reg .u64 t; cvta.to.shared.u64 t, %1; cvt.u32.u64 %0, t; }" : "=r"(a) : "l"(p));
    return a;
}

#define CP_ASYNC16(dst, src) \
    asm volatile("cp.async.cg.shared.global [%0], [%1], 16;" \
        :: "r"(dst), "l"(src) : "memory")
#define CP_COMMIT()  asm volatile("cp.async.commit_group;" ::: "memory")
#define CP_WAIT0()   asm volatile("cp.async.wait_group 0;" ::: "memory")

#define LDM_X4(r0, r1, r2, r3, addr) \
    asm volatile("ldmatrix.sync.aligned.m8n8.x4.shared.b16 {%0,%1,%2,%3}, [%4];" \
        : "=r"(r0), "=r"(r1), "=r"(r2), "=r"(r3) : "r"(addr))

#define MMA_FP16(c, a, b0v, b1v) \
    asm volatile("mma.sync.aligned.m16n8k16.row.col.f32.f16.f16.f32 " \
        "{%0,%1,%2,%3},{%4,%5,%6,%7},{%8,%9},{%0,%1,%2,%3};" \
        : "+f"((c)[0]), "+f"((c)[1]), "+f"((c)[2]), "+f"((c)[3]) \
        : "r"((a)[0]), "r"((a)[1]), "r"((a)[2]), "r"((a)[3]), "r"(b0v), "r"(b1v))

// ---------------- CSR build ----------------
__global__ void k_count(const int* __restrict__ dst, int E) {
    int e = blockIdx.x * blockDim.x + threadIdx.x;
    if (e < E) atomicAdd(&d_cnt[dst[e]], 1);
}

__global__ void k_scan1(int n) {
    __shared__ int wsum[32];
    int tid = threadIdx.x, lane = tid & 31, wrp = tid >> 5;
    int i = blockIdx.x * 1024 + tid;
    int v = (i < n) ? d_cnt[i] : 0;
    int x = v;
#pragma unroll
    for (int s = 1; s < 32; s <<= 1) {
        int t = __shfl_up_sync(0xFFFFFFFF, x, s);
        if (lane >= s) x += t;
    }
    if (lane == 31) wsum[wrp] = x;
    __syncthreads();
    if (wrp == 0) {
        int w = wsum[lane];
#pragma unroll
        for (int s = 1; s < 32; s <<= 1) {
            int t = __shfl_up_sync(0xFFFFFFFF, w, s);
            if (lane >= s) w += t;
        }
        wsum[lane] = w;
    }
    __syncthreads();
    int inc = x + (wrp > 0 ? wsum[wrp - 1] : 0);
    if (i < n) d_off[i] = inc - v;        // block-local exclusive
    if (tid == 1023) d_bsum[blockIdx.x] = inc;   // block total (raw)
}

// stage 2 (fused former scan2+scan3): each block sums raw block totals below it.
__global__ void k_scan3(int n, int nblk) {
    __shared__ int base;
    int bid = blockIdx.x;
    if (threadIdx.x == 0) {
        int s = 0;
        for (int j = 0; j < bid; ++j) s += d_bsum[j];
        base = s;
        if (bid == nblk - 1) d_off[n] = s + d_bsum[bid];
    }
    __syncthreads();
    int i = bid * 1024 + threadIdx.x;
    if (i >= n) return;
    int o = d_off[i] + base;
    int c = d_cnt[i];
    d_cnt[i] = 0;                 // self-clean for next replay
    d_off[i] = o;
    d_cur[i] = o;
    d_dinv[i] = rsqrtf((float)(c + 1));
}

__global__ void k_scatter(const int* __restrict__ src, const int* __restrict__ dst, int E) {
    int e = blockIdx.x * blockDim.x + threadIdx.x;
    if (e < E) {
        int d = dst[e];
        int p = atomicAdd(&d_cur[d], 1);
        d_ssrc[p] = src[e];
    }
}

// ---------------- layer-1 aggregation -> fp16 -------------------------------
__global__ void k_agg1(const int* __restrict__ ids, const float* __restrict__ feats,
                       const float* __restrict__ emb, int n) {
    int w = (blockIdx.x * blockDim.x + threadIdx.x) >> 5;
    int lane = threadIdx.x & 31;
    if (w >= n) return;
    int i = w;
    float di = d_dinv[i];
    float a0 = di * emb[(size_t)ids[i] * 32 + lane];
    float a1 = (lane < 4) ? di * feats[(size_t)i * 4 + lane] : 0.f;
    int e0 = d_off[i], e1 = d_off[i + 1];
    for (int e = e0; e < e1; ++e) {
        int s = d_ssrc[e];
        float c = d_dinv[s];
        a0 += c * emb[(size_t)ids[s] * 32 + lane];
        if (lane < 4) a1 += c * feats[(size_t)s * 4 + lane];
    }
    d_aggxh[(size_t)i * KP1 + lane] = __float2half_rn(di * a0);
    if (lane < 4) d_aggxh[(size_t)i * KP1 + 32 + lane] = __float2half_rn(di * a1);
}

// ---------------- prep weights ----------------------------------------------
__global__ void k_prepW1(const float* __restrict__ W1) {
    int idx = blockIdx.x * 256 + threadIdx.x;
    int n = idx & (HID1 - 1);
    int k = idx >> 11;
    d_w1t[(size_t)n * KP1 + k] = __float2half_rn(W1[(size_t)k * HID1 + n]);
}

__global__ void k_prepB(const float* __restrict__ W2) {
    __shared__ float t[32][33];
    int nt = blockIdx.x * 32, kt = blockIdx.y * 32;
    int x = threadIdx.x, y = threadIdx.y;
#pragma unroll
    for (int j = 0; j < 4; ++j)
        t[y + j * 8][x] = W2[(size_t)(kt + y + j * 8) * HID2 + nt + x];
    __syncthreads();
#pragma unroll
    for (int j = 0; j < 4; ++j) {
        float v = t[x][y + j * 8];
        d_w2t[(size_t)(nt + y + j * 8) * HID1 + kt + x] = __float2half_rn(v);
    }
}

// ---------------- GEMM1 via mma.sync fp16 (guard-free: NPAD rows) ----------
#define G1_ROWB 144
#define G1_MAT  (128 * G1_ROWB)

__global__ void __launch_bounds__(256) k_gemm1_mma(const float* __restrict__ bias) {
    __shared__ char smem[2 * G1_MAT];
    uint32_t sb = smem_to_u32(smem);
    const int tid = threadIdx.x;
    const int lane = tid & 31, wid = tid >> 5;
    const int wm = wid >> 2, wn = wid & 3;
    const int bn = blockIdx.x * 128;
    const int bm = blockIdx.y * 128;

#pragma unroll
    for (int i = 0; i < 4; ++i) {
        int idx = tid + i * 256;
        int row = idx >> 3, u = idx & 7;
        uint32_t so = (uint32_t)(row * G1_ROWB + u * 16);
        CP_ASYNC16(sb + so, (const char*)(d_aggxh + (size_t)(bm + row) * KP1 + u * 8));
        CP_ASYNC16(sb + G1_MAT + so,
                   (const char*)(d_w1t + (size_t)(bn + row) * KP1 + u * 8));
    }
    CP_COMMIT();

    float acc[4][4][4];
#pragma unroll
    for (int i = 0; i < 4; ++i)
#pragma unroll
        for (int j = 0; j < 4; ++j)
#pragma unroll
            for (int q = 0; q < 4; ++q) acc[i][j][q] = 0.f;

    CP_WAIT0();
    __syncthreads();

    const int lr = lane & 7;
    const int lm = lane >> 3;

    uint32_t bf[4][8];
#pragma unroll
    for (int nt = 0; nt < 4; ++nt) {
        uint32_t baddr = sb + G1_MAT +
            (uint32_t)((wn * 32 + nt * 8 + lr) * G1_ROWB + lm * 16);
        LDM_X4(bf[nt][0], bf[nt][1], bf[nt][2], bf[nt][3], baddr);
        LDM_X4(bf[nt][4], bf[nt][5], bf[nt][6], bf[nt][7], baddr + 64);
    }

#pragma unroll
    for (int ks = 0; ks < 4; ++ks) {
        uint32_t af[4][4];
#pragma unroll
        for (int mt = 0; mt < 4; ++mt) {
            uint32_t aaddr = sb +
                (uint32_t)((wm * 64 + mt * 16 + (lm & 1) * 8 + lr) * G1_ROWB +
                           ks * 32 + (lm >> 1) * 16);
            LDM_X4(af[mt][0], af[mt][1], af[mt][2], af[mt][3], aaddr);
        }
#pragma unroll
        for (int mt = 0; mt < 4; ++mt)
#pragma unroll
            for (int nt = 0; nt < 4; ++nt)
                MMA_FP16(acc[mt][nt], af[mt], bf[nt][2 * ks], bf[nt][2 * ks + 1]);
    }

    int r0 = lane >> 2;
    int c0 = (lane & 3) * 2;
#pragma unroll
    for (int nt = 0; nt < 4; ++nt) {
        int gcol = bn + wn * 32 + nt * 8 + c0;
        float b0 = bias[gcol], b1 = bias[gcol + 1];
#pragma unroll
        for (int mt = 0; mt < 4; ++mt) {
            int grow = bm + wm * 64 + mt * 16 + r0;
            *(__half2*)(d_h1h + (size_t)grow * HID1 + gcol) =
                __floats2half2_rn(fmaxf(acc[mt][nt][0] + b0, 0.f),
                                  fmaxf(acc[mt][nt][1] + b1, 0.f));
            *(__half2*)(d_h1h + (size_t)(grow + 8) * HID1 + gcol) =
                __floats2half2_rn(fmaxf(acc[mt][nt][2] + b0, 0.f),
                                  fmaxf(acc[mt][nt][3] + b1, 0.f));
        }
    }
}

// ---------------- GEMM2: block 128x64, warp 32x32, BK=64 (2 halves/sync) ----
#define G2_ROWB   144
#define G2_AMAT   (128 * G2_ROWB)
#define G2_BMAT   (64 * G2_ROWB)
#define G2_BUF    (G2_AMAT + G2_BMAT)
#define G2_SMEM   (2 * G2_BUF)

__global__ void __launch_bounds__(256, 3) k_gemm2_mma() {
    extern __shared__ char smem[];
    uint32_t sb = smem_to_u32(smem);
    const int tid = threadIdx.x;
    const int lane = tid & 31, wid = tid >> 5;
    const int wm = wid >> 1, wn = wid & 1;
    const int bn = blockIdx.x * 64;
    const int bm = blockIdx.y * 128;

    const int NCHUNK = HID1 / 64;   // 32

    auto fill = [&](int buf, int kt) {
        uint32_t base = sb + buf * G2_BUF;
#pragma unroll
        for (int i = 0; i < 4; ++i) {
            int idx = tid + i * 256;
            int row = idx >> 3;
            int u = idx & 7;
            uint32_t so = (uint32_t)(row * G2_ROWB + u * 16);
            CP_ASYNC16(base + so, (const char*)(d_h1h + (size_t)(bm + row) * HID1 + kt + u * 8));
        }
#pragma unroll
        for (int i = 0; i < 2; ++i) {
            int idx = tid + i * 256;
            int row = idx >> 3;
            int u = idx & 7;
            uint32_t so = (uint32_t)(row * G2_ROWB + u * 16);
            CP_ASYNC16(base + G2_AMAT + so,
                       (const char*)(d_w2t + (size_t)(bn + row) * HID1 + kt + u * 8));
        }
    };

    float acc[2][4][4];
#pragma unroll
    for (int i = 0; i < 2; ++i)
#pragma unroll
        for (int j = 0; j < 4; ++j)
#pragma unroll
            for (int q = 0; q < 4; ++q) acc[i][j][q] = 0.f;

    fill(0, 0);
    CP_COMMIT();
    CP_WAIT0();
    __syncthreads();

    const int lr = lane & 7;
    const int lm = lane >> 3;

    for (int c = 0; c < NCHUNK; ++c) {
        if (c + 1 < NCHUNK) {
            fill((c + 1) & 1, (c + 1) * 64);
            CP_COMMIT();
        }
        uint32_t base = sb + (c & 1) * G2_BUF;

#pragma unroll
        for (int half = 0; half < 2; ++half) {
            uint32_t bf[4][4];
#pragma unroll
            for (int nt = 0; nt < 4; ++nt) {
                uint32_t baddr = base + G2_AMAT +
                    (uint32_t)((wn * 32 + nt * 8 + lr) * G2_ROWB + half * 64 + lm * 16);
                LDM_X4(bf[nt][0], bf[nt][1], bf[nt][2], bf[nt][3], baddr);
            }
#pragma unroll
            for (int ks = 0; ks < 2; ++ks) {
                uint32_t af[2][4];
#pragma unroll
                for (int mt = 0; mt < 2; ++mt) {
                    uint32_t aaddr = base +
                        (uint32_t)((wm * 32 + mt * 16 + (lm & 1) * 8 + lr) * G2_ROWB +
                                   half * 64 + ks * 32 + (lm >> 1) * 16);
                    LDM_X4(af[mt][0], af[mt][1], af[mt][2], af[mt][3], aaddr);
                }
#pragma unroll
                for (int mt = 0; mt < 2; ++mt)
#pragma unroll
                    for (int nt = 0; nt < 4; ++nt)
                        MMA_FP16(acc[mt][nt], af[mt], bf[nt][2 * ks], bf[nt][2 * ks + 1]);
            }
        }
        CP_WAIT0();
        __syncthreads();
    }

    int r0 = lane >> 2;
    int c0 = (lane & 3) * 2;
#pragma unroll
    for (int mt = 0; mt < 2; ++mt) {
#pragma unroll
        for (int nt = 0; nt < 4; ++nt) {
            int grow = bm + wm * 32 + mt * 16 + r0;
            int gcol = bn + wn * 32 + nt * 8 + c0;
            *(__half2*)(d_yh + (size_t)grow * HID2 + gcol) =
                __floats2half2_rn(acc[mt][nt][0], acc[mt][nt][1]);
            *(__half2*)(d_yh + (size_t)(grow + 8) * HID2 + gcol) =
                __floats2half2_rn(acc[mt][nt][2], acc[mt][nt][3]);
        }
    }
}

// ---------------- layer-2 aggregation + bias + relu (2-way unrolled) --------
__global__ void k_agg2(const float* __restrict__ b2, int n) {
    int i = blockIdx.x;
    int tid = threadIdx.x;
    float di = d_dinv[i];
    const uint2* Y = (const uint2*)d_yh;
    uint2 raw = Y[(size_t)i * 256 + tid];
    float2 p0 = __half22float2(*(__half2*)&raw.x);
    float2 p1 = __half22float2(*(__half2*)&raw.y);
    float c0 = di * di;
    float4 acc = make_float4(p0.x * c0, p0.y * c0, p1.x * c0, p1.y * c0);
    int e0 = d_off[i], e1 = d_off[i + 1];
    int e = e0;
    for (; e + 1 < e1; e += 2) {
        int s0 = d_ssrc[e], s1 = d_ssrc[e + 1];
        float ca = di * d_dinv[s0];
        float cb = di * d_dinv[s1];
        uint2 ua = Y[(size_t)s0 * 256 + tid];
        uint2 ub = Y[(size_t)s1 * 256 + tid];
        float2 qa0 = __half22float2(*(__half2*)&ua.x);
        float2 qa1 = __half22float2(*(__half2*)&ua.y);
        float2 qb0 = __half22float2(*(__half2*)&ub.x);
        float2 qb1 = __half22float2(*(__half2*)&ub.y);
        acc.x += ca * qa0.x + cb * qb0.x;
        acc.y += ca * qa0.y + cb * qb0.y;
        acc.z += ca * qa1.x + cb * qb1.x;
        acc.w += ca * qa1.y + cb * qb1.y;
    }
    if (e < e1) {
        int s = d_ssrc[e];
        float c = di * d_dinv[s];
        uint2 u = Y[(size_t)s * 256 + tid];
        float2 q0 = __half22float2(*(__half2*)&u.x);
        float2 q1 = __half22float2(*(__half2*)&u.y);
        acc.x += c * q0.x;
        acc.y += c * q0.y;
        acc.z += c * q1.x;
        acc.w += c * q1.y;
    }
    float4 bb = ((const float4*)b2)[tid];
    uint2 out;
    *(__half2*)&out.x = __floats2half2_rn(fmaxf(acc.x + bb.x, 0.f),
                                          fmaxf(acc.y + bb.y, 0.f));
    *(__half2*)&out.y = __floats2half2_rn(fmaxf(acc.z + bb.z, 0.f),
                                          fmaxf(acc.w + bb.w, 0.f));
    ((uint2*)d_x2h)[(size_t)i * 256 + tid] = out;
}

// ---------------- mean pool per graph (2 blocks per graph) -------------------
__global__ void k_pool(const int* __restrict__ batch, int n) {
    int g = blockIdx.x;
    int tid = threadIdx.x;
    int cu = blockIdx.y * 256 + tid;          // u32 index 0..511 (2 cols each)
    int lo = 0, hi = n;
    while (lo < hi) { int m = (lo + hi) >> 1; if (batch[m] < g) lo = m + 1; else hi = m; }
    int s0 = lo;
    hi = n;
    while (lo < hi) { int m = (lo + hi) >> 1; if (batch[m] <= g) lo = m + 1; else hi = m; }
    int s1 = lo;
    float2 acc = make_float2(0.f, 0.f);
    const uint32_t* X = (const uint32_t*)d_x2h;
    for (int i = s0; i < s1; ++i) {
        uint32_t u = X[(size_t)i * 512 + cu];
        float2 q = __half22float2(*(__half2*)&u);
        acc.x += q.x;
        acc.y += q.y;
    }
    int c = s1 - s0;
    float inv = 1.f / (float)(c > 0 ? c : 1);
    *(float2*)(d_pooled + (size_t)g * 1024 + cu * 2) =
        make_float2(acc.x * inv, acc.y * inv);
}

// ---------------- MLP head ----------------------------------------------------
__global__ void k_mlp1(const float* __restrict__ W, const float* __restrict__ bias) {
    __shared__ float sp[1024];
    const int Kd = 1024, Nd = 1024;
    int g = blockIdx.x, cq = blockIdx.y, tid = threadIdx.x;
    for (int k = tid; k < Kd; k += 256) sp[k] = d_pooled[(size_t)g * Kd + k];
    __syncthreads();
    int c = cq * 256 + tid;
    float acc = bias[c];
#pragma unroll 4
    for (int k = 0; k < Kd; ++k)
        acc += sp[k] * W[(size_t)k * Nd + c];
    d_hh1[(size_t)g * Nd + c] = fmaxf(acc, 0.f);
}

// mlp2 fused with output layer: one block per graph, 2 cols/thread (512 cols),
// then block-reduce the 512-length dot against oW (2 classes).
__global__ void k_mlp2_out(const float* __restrict__ W, const float* __restrict__ bias,
                           const float* __restrict__ oW, const float* __restrict__ ob,
                           float* __restrict__ out) {
    __shared__ float sp[1024];
    __shared__ float h2s[512];
    __shared__ float red[512];
    const int Kd = 1024, Nd = 512;
    int g = blockIdx.x, tid = threadIdx.x;
    for (int k = tid; k < Kd; k += 256) sp[k] = d_hh1[(size_t)g * Kd + k];
    __syncthreads();
    int c = tid * 2;
    float a0 = bias[c], a1 = bias[c + 1];
#pragma unroll 4
    for (int k = 0; k < Kd; ++k) {
        float pk = sp[k];
        a0 += pk * W[(size_t)k * Nd + c];
        a1 += pk * W[(size_t)k * Nd + c + 1];
    }
    h2s[c] = fmaxf(a0, 0.f);
    h2s[c + 1] = fmaxf(a1, 0.f);
    __syncthreads();

    float o0 = 0.f, o1 = 0.f;
    for (int k = tid; k < 512; k += 256) {
        float h = h2s[k];
        o0 += h * oW[2 * k];
        o1 += h * oW[2 * k + 1];
    }
    red[tid] = o0;
    red[256 + tid] = o1;
    __syncthreads();
    for (int s = 128; s; s >>= 1) {
        if (tid < s) {
            red[tid] += red[tid + s];
            red[256 + tid] += red[256 + tid + s];
        }
        __syncthreads();
    }
    if (tid == 0) {
        out[g * 2] = red[0] + ob[0];
        out[g * 2 + 1] = red[256] + ob[1];
    }
}

// ---------------- launch ------------------------------------------------------
extern "C" void kernel_launch(void* const* d_in, const int* in_sizes, int n_in,
                              void* d_out, int out_size) {
    const int*   ids   = (const int*)  d_in[0];
    const float* feats = (const float*)d_in[1];
    const int*   eidx  = (const int*)  d_in[2];
    const int*   batch = (const int*)  d_in[3];
    const float* emb   = (const float*)d_in[4];
    const float* W1    = (const float*)d_in[5];
    const float* b1    = (const float*)d_in[6];
    const float* W2    = (const float*)d_in[7];
    const float* b2    = (const float*)d_in[8];
    const float* hW1   = (const float*)d_in[9];
    const float* hb1   = (const float*)d_in[10];
    const float* hW2   = (const float*)d_in[11];
    const float* hb2   = (const float*)d_in[12];
    const float* oW    = (const float*)d_in[13];
    const float* ob    = (const float*)d_in[14];

    int n = in_sizes[0];
    int E = in_sizes[2] / 2;
    int G = out_size / 2;

    const int* src = eidx;
    const int* dst = eidx + E;

    static bool attr_done = false;
    if (!attr_done) {
        cudaFuncSetAttribute(k_gemm2_mma, cudaFuncAttributeMaxDynamicSharedMemorySize,
                             G2_SMEM);
        attr_done = true;
    }

    int nblk = (n + 1023) / 1024;

    k_count<<<(E + 255) / 256, 256>>>(dst, E);
    k_scan1<<<nblk, 1024>>>(n);
    k_scan3<<<nblk, 1024>>>(n, nblk);
    k_scatter<<<(E + 255) / 256, 256>>>(src, dst, E);

    k_prepW1<<<(DIN * HID1) / 256, 256>>>(W1);
    dim3 gp(HID2 / 32, HID1 / 32);
    k_prepB<<<gp, dim3(32, 8)>>>(W2);

    k_agg1<<<(n + 7) / 8, 256>>>(ids, feats, emb, n);

    dim3 g1(HID1 / 128, (n + 127) / 128);
    k_gemm1_mma<<<g1, 256>>>(b1);

    dim3 g2(HID2 / 64, (n + 127) / 128);
    k_gemm2_mma<<<g2, 256, G2_SMEM>>>();

    k_agg2<<<n, 256>>>(b2, n);

    k_pool<<<dim3(G, 2), 256>>>(batch, n);

    k_mlp1<<<dim3(G, 4), 256>>>(hW1, hb1);
    k_mlp2_out<<<G, 256>>>(hW2, hb2, oW, ob, (float*)d_out);
}

// round 15
// speedup vs baseline: 1.1478x; 1.0251x over previous
#include <cuda_runtime.h>
#include <cuda_fp16.h>
#include <stdint.h>

// Problem constants
#define NMAX 20000
#define NPAD 20096
#define EMAX 160000
#define GMAX 64
#define DIN  36
#define KP1  64
#define HID1 2048
#define HID2 1024

// ---------------- scratch (device globals, no runtime alloc) ----------------
__device__ float d_dinv[NMAX];
__device__ int   d_cnt[NMAX];
__device__ int   d_off[NMAX + 1];
__device__ int   d_cur[NMAX];
__device__ int   d_bsum[32];
__device__ int   d_ssrc[EMAX];
__device__ __half d_aggxh[(size_t)NPAD * KP1];   // rows >= n stay zero
__device__ __half d_w1t[(size_t)HID1 * KP1];
__device__ __half d_h1h[(size_t)NPAD * HID1];    // rows >= n stay zero
__device__ __half d_w2t[(size_t)HID2 * HID1];
__device__ __half d_yh[(size_t)NPAD * HID2];     // padded: guard-free epilogue
__device__ __half d_x2h[(size_t)NMAX * HID2];
__device__ float d_pooled[GMAX * HID2];
__device__ float d_hh1[GMAX * 1024];

// ---------------- PTX helpers (base ISA) ------------------------------------
__device__ __forceinline__ uint32_t smem_to_u32(const void* p) {
    uint32_t a;
    asm("{ .reg .u64 t; cvta.to.shared.u64 t, %1; cvt.u32.u64 %0, t; }" : "=r"(a) : "l"(p));
    return a;
}

#define CP_ASYNC16(dst, src) \
    asm volatile("cp.async.cg.shared.global [%0], [%1], 16;" \
        :: "r"(dst), "l"(src) : "memory")
#define CP_COMMIT()  asm volatile("cp.async.commit_group;" ::: "memory")
#define CP_WAIT0()   asm volatile("cp.async.wait_group 0;" ::: "memory")

#define LDM_X4(r0, r1, r2, r3, addr) \
    asm volatile("ldmatrix.sync.aligned.m8n8.x4.shared.b16 {%0,%1,%2,%3}, [%4];" \
        : "=r"(r0), "=r"(r1), "=r"(r2), "=r"(r3) : "r"(addr))

#define MMA_FP16(c, a, b0v, b1v) \
    asm volatile("mma.sync.aligned.m16n8k16.row.col.f32.f16.f16.f32 " \
        "{%0,%1,%2,%3},{%4,%5,%6,%7},{%8,%9},{%0,%1,%2,%3};" \
        : "+f"((c)[0]), "+f"((c)[1]), "+f"((c)[2]), "+f"((c)[3]) \
        : "r"((a)[0]), "r"((a)[1]), "r"((a)[2]), "r"((a)[3]), "r"(b0v), "r"(b1v))

// ---------------- CSR build ----------------
__global__ void k_count(const int* __restrict__ dst, int E) {
    int e = blockIdx.x * blockDim.x + threadIdx.x;
    if (e < E) atomicAdd(&d_cnt[dst[e]], 1);
}

__global__ void k_scan1(int n) {
    __shared__ int wsum[32];
    int tid = threadIdx.x, lane = tid & 31, wrp = tid >> 5;
    int i = blockIdx.x * 1024 + tid;
    int v = (i < n) ? d_cnt[i] : 0;
    int x = v;
#pragma unroll
    for (int s = 1; s < 32; s <<= 1) {
        int t = __shfl_up_sync(0xFFFFFFFF, x, s);
        if (lane >= s) x += t;
    }
    if (lane == 31) wsum[wrp] = x;
    __syncthreads();
    if (wrp == 0) {
        int w = wsum[lane];
#pragma unroll
        for (int s = 1; s < 32; s <<= 1) {
            int t = __shfl_up_sync(0xFFFFFFFF, w, s);
            if (lane >= s) w += t;
        }
        wsum[lane] = w;
    }
    __syncthreads();
    int inc = x + (wrp > 0 ? wsum[wrp - 1] : 0);
    if (i < n) d_off[i] = inc - v;        // block-local exclusive
    if (tid == 1023) d_bsum[blockIdx.x] = inc;   // block total (raw)
}

// stage 2 (fused scan2+scan3): each block sums raw block totals below it.
__global__ void k_scan3(int n, int nblk) {
    __shared__ int base;
    int bid = blockIdx.x;
    if (threadIdx.x == 0) {
        int s = 0;
        for (int j = 0; j < bid; ++j) s += d_bsum[j];
        base = s;
        if (bid == nblk - 1) d_off[n] = s + d_bsum[bid];
    }
    __syncthreads();
    int i = bid * 1024 + threadIdx.x;
    if (i >= n) return;
    int o = d_off[i] + base;
    int c = d_cnt[i];
    d_cnt[i] = 0;                 // self-clean for next replay
    d_off[i] = o;
    d_cur[i] = o;
    d_dinv[i] = rsqrtf((float)(c + 1));
}

__global__ void k_scatter(const int* __restrict__ src, const int* __restrict__ dst, int E) {
    int e = blockIdx.x * blockDim.x + threadIdx.x;
    if (e < E) {
        int d = dst[e];
        int p = atomicAdd(&d_cur[d], 1);
        d_ssrc[p] = src[e];
    }
}

// ---------------- layer-1 aggregation -> fp16 -------------------------------
__global__ void k_agg1(const int* __restrict__ ids, const float* __restrict__ feats,
                       const float* __restrict__ emb, int n) {
    int w = (blockIdx.x * blockDim.x + threadIdx.x) >> 5;
    int lane = threadIdx.x & 31;
    if (w >= n) return;
    int i = w;
    float di = d_dinv[i];
    float a0 = di * emb[(size_t)ids[i] * 32 + lane];
    float a1 = (lane < 4) ? di * feats[(size_t)i * 4 + lane] : 0.f;
    int e0 = d_off[i], e1 = d_off[i + 1];
    for (int e = e0; e < e1; ++e) {
        int s = d_ssrc[e];
        float c = d_dinv[s];
        a0 += c * emb[(size_t)ids[s] * 32 + lane];
        if (lane < 4) a1 += c * feats[(size_t)s * 4 + lane];
    }
    d_aggxh[(size_t)i * KP1 + lane] = __float2half_rn(di * a0);
    if (lane < 4) d_aggxh[(size_t)i * KP1 + 32 + lane] = __float2half_rn(di * a1);
}

// ---------------- prep weights ----------------------------------------------
__global__ void k_prepW1(const float* __restrict__ W1) {
    int idx = blockIdx.x * 256 + threadIdx.x;
    int n = idx & (HID1 - 1);
    int k = idx >> 11;
    d_w1t[(size_t)n * KP1 + k] = __float2half_rn(W1[(size_t)k * HID1 + n]);
}

__global__ void k_prepB(const float* __restrict__ W2) {
    __shared__ float t[32][33];
    int nt = blockIdx.x * 32, kt = blockIdx.y * 32;
    int x = threadIdx.x, y = threadIdx.y;
#pragma unroll
    for (int j = 0; j < 4; ++j)
        t[y + j * 8][x] = W2[(size_t)(kt + y + j * 8) * HID2 + nt + x];
    __syncthreads();
#pragma unroll
    for (int j = 0; j < 4; ++j) {
        float v = t[x][y + j * 8];
        d_w2t[(size_t)(nt + y + j * 8) * HID1 + kt + x] = __float2half_rn(v);
    }
}

// ---------------- GEMM1 via mma.sync fp16 (guard-free: NPAD rows) ----------
#define G1_ROWB 144
#define G1_MAT  (128 * G1_ROWB)

__global__ void __launch_bounds__(256) k_gemm1_mma(const float* __restrict__ bias) {
    __shared__ char smem[2 * G1_MAT];
    uint32_t sb = smem_to_u32(smem);
    const int tid = threadIdx.x;
    const int lane = tid & 31, wid = tid >> 5;
    const int wm = wid >> 2, wn = wid & 3;
    const int bn = blockIdx.x * 128;
    const int bm = blockIdx.y * 128;

#pragma unroll
    for (int i = 0; i < 4; ++i) {
        int idx = tid + i * 256;
        int row = idx >> 3, u = idx & 7;
        uint32_t so = (uint32_t)(row * G1_ROWB + u * 16);
        CP_ASYNC16(sb + so, (const char*)(d_aggxh + (size_t)(bm + row) * KP1 + u * 8));
        CP_ASYNC16(sb + G1_MAT + so,
                   (const char*)(d_w1t + (size_t)(bn + row) * KP1 + u * 8));
    }
    CP_COMMIT();

    float acc[4][4][4];
#pragma unroll
    for (int i = 0; i < 4; ++i)
#pragma unroll
        for (int j = 0; j < 4; ++j)
#pragma unroll
            for (int q = 0; q < 4; ++q) acc[i][j][q] = 0.f;

    CP_WAIT0();
    __syncthreads();

    const int lr = lane & 7;
    const int lm = lane >> 3;

    uint32_t bf[4][8];
#pragma unroll
    for (int nt = 0; nt < 4; ++nt) {
        uint32_t baddr = sb + G1_MAT +
            (uint32_t)((wn * 32 + nt * 8 + lr) * G1_ROWB + lm * 16);
        LDM_X4(bf[nt][0], bf[nt][1], bf[nt][2], bf[nt][3], baddr);
        LDM_X4(bf[nt][4], bf[nt][5], bf[nt][6], bf[nt][7], baddr + 64);
    }

#pragma unroll
    for (int ks = 0; ks < 4; ++ks) {
        uint32_t af[4][4];
#pragma unroll
        for (int mt = 0; mt < 4; ++mt) {
            uint32_t aaddr = sb +
                (uint32_t)((wm * 64 + mt * 16 + (lm & 1) * 8 + lr) * G1_ROWB +
                           ks * 32 + (lm >> 1) * 16);
            LDM_X4(af[mt][0], af[mt][1], af[mt][2], af[mt][3], aaddr);
        }
#pragma unroll
        for (int mt = 0; mt < 4; ++mt)
#pragma unroll
            for (int nt = 0; nt < 4; ++nt)
                MMA_FP16(acc[mt][nt], af[mt], bf[nt][2 * ks], bf[nt][2 * ks + 1]);
    }

    int r0 = lane >> 2;
    int c0 = (lane & 3) * 2;
#pragma unroll
    for (int nt = 0; nt < 4; ++nt) {
        int gcol = bn + wn * 32 + nt * 8 + c0;
        float b0 = bias[gcol], b1 = bias[gcol + 1];
#pragma unroll
        for (int mt = 0; mt < 4; ++mt) {
            int grow = bm + wm * 64 + mt * 16 + r0;
            *(__half2*)(d_h1h + (size_t)grow * HID1 + gcol) =
                __floats2half2_rn(fmaxf(acc[mt][nt][0] + b0, 0.f),
                                  fmaxf(acc[mt][nt][1] + b1, 0.f));
            *(__half2*)(d_h1h + (size_t)(grow + 8) * HID1 + gcol) =
                __floats2half2_rn(fmaxf(acc[mt][nt][2] + b0, 0.f),
                                  fmaxf(acc[mt][nt][3] + b1, 0.f));
        }
    }
}

// ---------------- GEMM2: block 64x64, 4 warps (warp 32x32), BK=64 -----------
// 128-thread CTAs: each __syncthreads drains only 4 warps, and 6 CTAs/SM
// (same 24 warps/SM) keep 5 independent CTAs running through any one CTA's
// barrier. Same BK=64 two-half structure / register footprint as R13 best.
#define G2_ROWB   144
#define G2_AMAT   (64 * G2_ROWB)           // 9216
#define G2_BMAT   (64 * G2_ROWB)           // 9216
#define G2_BUF    (G2_AMAT + G2_BMAT)      // 18432
#define G2_SMEM   (2 * G2_BUF)             // 36864

__global__ void __launch_bounds__(128, 6) k_gemm2_mma() {
    extern __shared__ char smem[];
    uint32_t sb = smem_to_u32(smem);
    const int tid = threadIdx.x;
    const int lane = tid & 31, wid = tid >> 5;
    const int wm = wid >> 1, wn = wid & 1;       // 2(m) x 2(n)
    const int bn = blockIdx.x * 64;
    const int bm = blockIdx.y * 64;

    const int NCHUNK = HID1 / 64;   // 32

    // fill one buffer: A 512 units + B 512 units = 8 cp.async/thread
    auto fill = [&](int buf, int kt) {
        uint32_t base = sb + buf * G2_BUF;
#pragma unroll
        for (int i = 0; i < 4; ++i) {
            int idx = tid + i * 128;        // 0..511
            int row = idx >> 3;
            int u = idx & 7;
            uint32_t so = (uint32_t)(row * G2_ROWB + u * 16);
            CP_ASYNC16(base + so, (const char*)(d_h1h + (size_t)(bm + row) * HID1 + kt + u * 8));
        }
#pragma unroll
        for (int i = 0; i < 4; ++i) {
            int idx = tid + i * 128;        // 0..511
            int row = idx >> 3;
            int u = idx & 7;
            uint32_t so = (uint32_t)(row * G2_ROWB + u * 16);
            CP_ASYNC16(base + G2_AMAT + so,
                       (const char*)(d_w2t + (size_t)(bn + row) * HID1 + kt + u * 8));
        }
    };

    float acc[2][4][4];
#pragma unroll
    for (int i = 0; i < 2; ++i)
#pragma unroll
        for (int j = 0; j < 4; ++j)
#pragma unroll
            for (int q = 0; q < 4; ++q) acc[i][j][q] = 0.f;

    fill(0, 0);
    CP_COMMIT();
    CP_WAIT0();
    __syncthreads();

    const int lr = lane & 7;
    const int lm = lane >> 3;

    for (int c = 0; c < NCHUNK; ++c) {
        if (c + 1 < NCHUNK) {
            fill((c + 1) & 1, (c + 1) * 64);
            CP_COMMIT();
        }
        uint32_t base = sb + (c & 1) * G2_BUF;

#pragma unroll
        for (int half = 0; half < 2; ++half) {
            uint32_t bf[4][4];
#pragma unroll
            for (int nt = 0; nt < 4; ++nt) {
                uint32_t baddr = base + G2_AMAT +
                    (uint32_t)((wn * 32 + nt * 8 + lr) * G2_ROWB + half * 64 + lm * 16);
                LDM_X4(bf[nt][0], bf[nt][1], bf[nt][2], bf[nt][3], baddr);
            }
#pragma unroll
            for (int ks = 0; ks < 2; ++ks) {
                uint32_t af[2][4];
#pragma unroll
                for (int mt = 0; mt < 2; ++mt) {
                    uint32_t aaddr = base +
                        (uint32_t)((wm * 32 + mt * 16 + (lm & 1) * 8 + lr) * G2_ROWB +
                                   half * 64 + ks * 32 + (lm >> 1) * 16);
                    LDM_X4(af[mt][0], af[mt][1], af[mt][2], af[mt][3], aaddr);
                }
#pragma unroll
                for (int mt = 0; mt < 2; ++mt)
#pragma unroll
                    for (int nt = 0; nt < 4; ++nt)
                        MMA_FP16(acc[mt][nt], af[mt], bf[nt][2 * ks], bf[nt][2 * ks + 1]);
            }
        }
        CP_WAIT0();
        __syncthreads();
    }

    int r0 = lane >> 2;
    int c0 = (lane & 3) * 2;
#pragma unroll
    for (int mt = 0; mt < 2; ++mt) {
#pragma unroll
        for (int nt = 0; nt < 4; ++nt) {
            int grow = bm + wm * 32 + mt * 16 + r0;
            int gcol = bn + wn * 32 + nt * 8 + c0;
            *(__half2*)(d_yh + (size_t)grow * HID2 + gcol) =
                __floats2half2_rn(acc[mt][nt][0], acc[mt][nt][1]);
            *(__half2*)(d_yh + (size_t)(grow + 8) * HID2 + gcol) =
                __floats2half2_rn(acc[mt][nt][2], acc[mt][nt][3]);
        }
    }
}

// ---------------- layer-2 aggregation + bias + relu (2-way unrolled) --------
__global__ void k_agg2(const float* __restrict__ b2, int n) {
    int i = blockIdx.x;
    int tid = threadIdx.x;
    float di = d_dinv[i];
    const uint2* Y = (const uint2*)d_yh;
    uint2 raw = Y[(size_t)i * 256 + tid];
    float2 p0 = __half22float2(*(__half2*)&raw.x);
    float2 p1 = __half22float2(*(__half2*)&raw.y);
    float c0 = di * di;
    float4 acc = make_float4(p0.x * c0, p0.y * c0, p1.x * c0, p1.y * c0);
    int e0 = d_off[i], e1 = d_off[i + 1];
    int e = e0;
    for (; e + 1 < e1; e += 2) {
        int s0 = d_ssrc[e], s1 = d_ssrc[e + 1];
        float ca = di * d_dinv[s0];
        float cb = di * d_dinv[s1];
        uint2 ua = Y[(size_t)s0 * 256 + tid];
        uint2 ub = Y[(size_t)s1 * 256 + tid];
        float2 qa0 = __half22float2(*(__half2*)&ua.x);
        float2 qa1 = __half22float2(*(__half2*)&ua.y);
        float2 qb0 = __half22float2(*(__half2*)&ub.x);
        float2 qb1 = __half22float2(*(__half2*)&ub.y);
        acc.x += ca * qa0.x + cb * qb0.x;
        acc.y += ca * qa0.y + cb * qb0.y;
        acc.z += ca * qa1.x + cb * qb1.x;
        acc.w += ca * qa1.y + cb * qb1.y;
    }
    if (e < e1) {
        int s = d_ssrc[e];
        float c = di * d_dinv[s];
        uint2 u = Y[(size_t)s * 256 + tid];
        float2 q0 = __half22float2(*(__half2*)&u.x);
        float2 q1 = __half22float2(*(__half2*)&u.y);
        acc.x += c * q0.x;
        acc.y += c * q0.y;
        acc.z += c * q1.x;
        acc.w += c * q1.y;
    }
    float4 bb = ((const float4*)b2)[tid];
    uint2 out;
    *(__half2*)&out.x = __floats2half2_rn(fmaxf(acc.x + bb.x, 0.f),
                                          fmaxf(acc.y + bb.y, 0.f));
    *(__half2*)&out.y = __floats2half2_rn(fmaxf(acc.z + bb.z, 0.f),
                                          fmaxf(acc.w + bb.w, 0.f));
    ((uint2*)d_x2h)[(size_t)i * 256 + tid] = out;
}

// ---------------- mean pool per graph (2 blocks per graph) -------------------
__global__ void k_pool(const int* __restrict__ batch, int n) {
    int g = blockIdx.x;
    int tid = threadIdx.x;
    int cu = blockIdx.y * 256 + tid;          // u32 index 0..511 (2 cols each)
    int lo = 0, hi = n;
    while (lo < hi) { int m = (lo + hi) >> 1; if (batch[m] < g) lo = m + 1; else hi = m; }
    int s0 = lo;
    hi = n;
    while (lo < hi) { int m = (lo + hi) >> 1; if (batch[m] <= g) lo = m + 1; else hi = m; }
    int s1 = lo;
    float2 acc = make_float2(0.f, 0.f);
    const uint32_t* X = (const uint32_t*)d_x2h;
    for (int i = s0; i < s1; ++i) {
        uint32_t u = X[(size_t)i * 512 + cu];
        float2 q = __half22float2(*(__half2*)&u);
        acc.x += q.x;
        acc.y += q.y;
    }
    int c = s1 - s0;
    float inv = 1.f / (float)(c > 0 ? c : 1);
    *(float2*)(d_pooled + (size_t)g * 1024 + cu * 2) =
        make_float2(acc.x * inv, acc.y * inv);
}

// ---------------- MLP head ----------------------------------------------------
__global__ void k_mlp1(const float* __restrict__ W, const float* __restrict__ bias) {
    __shared__ float sp[1024];
    const int Kd = 1024, Nd = 1024;
    int g = blockIdx.x, cq = blockIdx.y, tid = threadIdx.x;
    for (int k = tid; k < Kd; k += 256) sp[k] = d_pooled[(size_t)g * Kd + k];
    __syncthreads();
    int c = cq * 256 + tid;
    float acc = bias[c];
#pragma unroll 4
    for (int k = 0; k < Kd; ++k)
        acc += sp[k] * W[(size_t)k * Nd + c];
    d_hh1[(size_t)g * Nd + c] = fmaxf(acc, 0.f);
}

// mlp2 fused with output layer
__global__ void k_mlp2_out(const float* __restrict__ W, const float* __restrict__ bias,
                           const float* __restrict__ oW, const float* __restrict__ ob,
                           float* __restrict__ out) {
    __shared__ float sp[1024];
    __shared__ float h2s[512];
    __shared__ float red[512];
    const int Kd = 1024, Nd = 512;
    int g = blockIdx.x, tid = threadIdx.x;
    for (int k = tid; k < Kd; k += 256) sp[k] = d_hh1[(size_t)g * Kd + k];
    __syncthreads();
    int c = tid * 2;
    float a0 = bias[c], a1 = bias[c + 1];
#pragma unroll 4
    for (int k = 0; k < Kd; ++k) {
        float pk = sp[k];
        a0 += pk * W[(size_t)k * Nd + c];
        a1 += pk * W[(size_t)k * Nd + c + 1];
    }
    h2s[c] = fmaxf(a0, 0.f);
    h2s[c + 1] = fmaxf(a1, 0.f);
    __syncthreads();

    float o0 = 0.f, o1 = 0.f;
    for (int k = tid; k < 512; k += 256) {
        float h = h2s[k];
        o0 += h * oW[2 * k];
        o1 += h * oW[2 * k + 1];
    }
    red[tid] = o0;
    red[256 + tid] = o1;
    __syncthreads();
    for (int s = 128; s; s >>= 1) {
        if (tid < s) {
            red[tid] += red[tid + s];
            red[256 + tid] += red[256 + tid + s];
        }
        __syncthreads();
    }
    if (tid == 0) {
        out[g * 2] = red[0] + ob[0];
        out[g * 2 + 1] = red[256] + ob[1];
    }
}

// ---------------- launch ------------------------------------------------------
extern "C" void kernel_launch(void* const* d_in, const int* in_sizes, int n_in,
                              void* d_out, int out_size) {
    const int*   ids   = (const int*)  d_in[0];
    const float* feats = (const float*)d_in[1];
    const int*   eidx  = (const int*)  d_in[2];
    const int*   batch = (const int*)  d_in[3];
    const float* emb   = (const float*)d_in[4];
    const float* W1    = (const float*)d_in[5];
    const float* b1    = (const float*)d_in[6];
    const float* W2    = (const float*)d_in[7];
    const float* b2    = (const float*)d_in[8];
    const float* hW1   = (const float*)d_in[9];
    const float* hb1   = (const float*)d_in[10];
    const float* hW2   = (const float*)d_in[11];
    const float* hb2   = (const float*)d_in[12];
    const float* oW    = (const float*)d_in[13];
    const float* ob    = (const float*)d_in[14];

    int n = in_sizes[0];
    int E = in_sizes[2] / 2;
    int G = out_size / 2;

    const int* src = eidx;
    const int* dst = eidx + E;

    static bool attr_done = false;
    if (!attr_done) {
        cudaFuncSetAttribute(k_gemm2_mma, cudaFuncAttributeMaxDynamicSharedMemorySize,
                             G2_SMEM);
        attr_done = true;
    }

    int nblk = (n + 1023) / 1024;

    k_count<<<(E + 255) / 256, 256>>>(dst, E);
    k_scan1<<<nblk, 1024>>>(n);
    k_scan3<<<nblk, 1024>>>(n, nblk);
    k_scatter<<<(E + 255) / 256, 256>>>(src, dst, E);

    k_prepW1<<<(DIN * HID1) / 256, 256>>>(W1);
    dim3 gp(HID2 / 32, HID1 / 32);
    k_prepB<<<gp, dim3(32, 8)>>>(W2);

    k_agg1<<<(n + 7) / 8, 256>>>(ids, feats, emb, n);

    dim3 g1(HID1 / 128, (n + 127) / 128);
    k_gemm1_mma<<<g1, 256>>>(b1);

    dim3 g2(HID2 / 64, (n + 63) / 64);
    k_gemm2_mma<<<g2, 128, G2_SMEM>>>();

    k_agg2<<<n, 256>>>(b2, n);

    k_pool<<<dim3(G, 2), 256>>>(batch, n);

    k_mlp1<<<dim3(G, 4), 256>>>(hW1, hb1);
    k_mlp2_out<<<G, 256>>>(hW2, hb2, oW, ob, (float*)d_out);
}

// round 16
// speedup vs baseline: 1.1563x; 1.0074x over previous
#include <cuda_runtime.h>
#include <cuda_fp16.h>
#include <stdint.h>

// Problem constants
#define NMAX 20000
#define NPAD 20096
#define EMAX 160000
#define GMAX 64
#define DIN  36
#define KP1  64
#define HID1 2048
#define HID2 1024

// ---------------- scratch (device globals, no runtime alloc) ----------------
__device__ float d_dinv[NMAX];
__device__ int   d_cnt[NMAX];
__device__ int   d_off[NMAX + 1];
__device__ int   d_cur[NMAX];
__device__ int   d_bsum[32];
__device__ int   d_ssrc[EMAX];
__device__ __half d_aggxh[(size_t)NPAD * KP1];   // rows >= n stay zero
__device__ __half d_w1t[(size_t)HID1 * KP1];
__device__ __half d_h1h[(size_t)NPAD * HID1];    // rows >= n stay zero
__device__ __half d_w2t[(size_t)HID2 * HID1];
__device__ __half d_yh[(size_t)NPAD * HID2];     // padded: guard-free epilogue
__device__ __half d_x2h[(size_t)NMAX * HID2];
__device__ float d_pooled[GMAX * HID2];
__device__ float d_hh1[GMAX * 1024];

// ---------------- PTX helpers (base ISA) ------------------------------------
__device__ __forceinline__ uint32_t smem_to_u32(const void* p) {
    uint32_t a;
    asm("{ .reg .u64 t; cvta.to.shared.u64 t, %1; cvt.u32.u64 %0, t; }" : "=r"(a) : "l"(p));
    return a;
}

#define CP_ASYNC16(dst, src) \
    asm volatile("cp.async.cg.shared.global [%0], [%1], 16;" \
        :: "r"(dst), "l"(src) : "memory")
#define CP_COMMIT()  asm volatile("cp.async.commit_group;" ::: "memory")
#define CP_WAIT0()   asm volatile("cp.async.wait_group 0;" ::: "memory")

#define LDM_X4(r0, r1, r2, r3, addr) \
    asm volatile("ldmatrix.sync.aligned.m8n8.x4.shared.b16 {%0,%1,%2,%3}, [%4];" \
        : "=r"(r0), "=r"(r1), "=r"(r2), "=r"(r3) : "r"(addr))

#define MMA_FP16(c, a, b0v, b1v) \
    asm volatile("mma.sync.aligned.m16n8k16.row.col.f32.f16.f16.f32 " \
        "{%0,%1,%2,%3},{%4,%5,%6,%7},{%8,%9},{%0,%1,%2,%3};" \
        : "+f"((c)[0]), "+f"((c)[1]), "+f"((c)[2]), "+f"((c)[3]) \
        : "r"((a)[0]), "r"((a)[1]), "r"((a)[2]), "r"((a)[3]), "r"(b0v), "r"(b1v))

// ---------------- CSR build ----------------
__global__ void k_count(const int* __restrict__ dst, int E) {
    int e = blockIdx.x * blockDim.x + threadIdx.x;
    if (e < E) atomicAdd(&d_cnt[dst[e]], 1);
}

__global__ void k_scan1(int n) {
    __shared__ int wsum[32];
    int tid = threadIdx.x, lane = tid & 31, wrp = tid >> 5;
    int i = blockIdx.x * 1024 + tid;
    int v = (i < n) ? d_cnt[i] : 0;
    int x = v;
#pragma unroll
    for (int s = 1; s < 32; s <<= 1) {
        int t = __shfl_up_sync(0xFFFFFFFF, x, s);
        if (lane >= s) x += t;
    }
    if (lane == 31) wsum[wrp] = x;
    __syncthreads();
    if (wrp == 0) {
        int w = wsum[lane];
#pragma unroll
        for (int s = 1; s < 32; s <<= 1) {
            int t = __shfl_up_sync(0xFFFFFFFF, w, s);
            if (lane >= s) w += t;
        }
        wsum[lane] = w;
    }
    __syncthreads();
    int inc = x + (wrp > 0 ? wsum[wrp - 1] : 0);
    if (i < n) d_off[i] = inc - v;        // block-local exclusive
    if (tid == 1023) d_bsum[blockIdx.x] = inc;   // block total (raw)
}

// stage 2 (fused scan2+scan3): each block sums raw block totals below it.
__global__ void k_scan3(int n, int nblk) {
    __shared__ int base;
    int bid = blockIdx.x;
    if (threadIdx.x == 0) {
        int s = 0;
        for (int j = 0; j < bid; ++j) s += d_bsum[j];
        base = s;
        if (bid == nblk - 1) d_off[n] = s + d_bsum[bid];
    }
    __syncthreads();
    int i = bid * 1024 + threadIdx.x;
    if (i >= n) return;
    int o = d_off[i] + base;
    int c = d_cnt[i];
    d_cnt[i] = 0;                 // self-clean for next replay
    d_off[i] = o;
    d_cur[i] = o;
    d_dinv[i] = rsqrtf((float)(c + 1));
}

__global__ void k_scatter(const int* __restrict__ src, const int* __restrict__ dst, int E) {
    int e = blockIdx.x * blockDim.x + threadIdx.x;
    if (e < E) {
        int d = dst[e];
        int p = atomicAdd(&d_cur[d], 1);
        d_ssrc[p] = src[e];
    }
}

// ---------------- layer-1 aggregation -> fp16 (2-edge unrolled) --------------
__global__ void k_agg1(const int* __restrict__ ids, const float* __restrict__ feats,
                       const float* __restrict__ emb, int n) {
    int w = (blockIdx.x * blockDim.x + threadIdx.x) >> 5;
    int lane = threadIdx.x & 31;
    if (w >= n) return;
    int i = w;
    float di = d_dinv[i];
    float a0 = di * emb[(size_t)ids[i] * 32 + lane];
    float a1 = (lane < 4) ? di * feats[(size_t)i * 4 + lane] : 0.f;
    int e0 = d_off[i], e1 = d_off[i + 1];
    int e = e0;
    for (; e + 1 < e1; e += 2) {
        int sA = d_ssrc[e], sB = d_ssrc[e + 1];
        float cA = d_dinv[sA], cB = d_dinv[sB];
        float vA = emb[(size_t)ids[sA] * 32 + lane];
        float vB = emb[(size_t)ids[sB] * 32 + lane];
        a0 += cA * vA + cB * vB;
        if (lane < 4)
            a1 += cA * feats[(size_t)sA * 4 + lane] + cB * feats[(size_t)sB * 4 + lane];
    }
    if (e < e1) {
        int s = d_ssrc[e];
        float c = d_dinv[s];
        a0 += c * emb[(size_t)ids[s] * 32 + lane];
        if (lane < 4) a1 += c * feats[(size_t)s * 4 + lane];
    }
    d_aggxh[(size_t)i * KP1 + lane] = __float2half_rn(di * a0);
    if (lane < 4) d_aggxh[(size_t)i * KP1 + 32 + lane] = __float2half_rn(di * a1);
}

// ---------------- prep weights ----------------------------------------------
__global__ void k_prepW1(const float* __restrict__ W1) {
    int idx = blockIdx.x * 256 + threadIdx.x;
    int n = idx & (HID1 - 1);
    int k = idx >> 11;
    d_w1t[(size_t)n * KP1 + k] = __float2half_rn(W1[(size_t)k * HID1 + n]);
}

__global__ void k_prepB(const float* __restrict__ W2) {
    __shared__ float t[32][33];
    int nt = blockIdx.x * 32, kt = blockIdx.y * 32;
    int x = threadIdx.x, y = threadIdx.y;
#pragma unroll
    for (int j = 0; j < 4; ++j)
        t[y + j * 8][x] = W2[(size_t)(kt + y + j * 8) * HID2 + nt + x];
    __syncthreads();
#pragma unroll
    for (int j = 0; j < 4; ++j) {
        float v = t[x][y + j * 8];
        d_w2t[(size_t)(nt + y + j * 8) * HID1 + kt + x] = __float2half_rn(v);
    }
}

// ---------------- GEMM1 via mma.sync fp16 (guard-free: NPAD rows) ----------
#define G1_ROWB 144
#define G1_MAT  (128 * G1_ROWB)

__global__ void __launch_bounds__(256) k_gemm1_mma(const float* __restrict__ bias) {
    __shared__ char smem[2 * G1_MAT];
    uint32_t sb = smem_to_u32(smem);
    const int tid = threadIdx.x;
    const int lane = tid & 31, wid = tid >> 5;
    const int wm = wid >> 2, wn = wid & 3;
    const int bn = blockIdx.x * 128;
    const int bm = blockIdx.y * 128;

#pragma unroll
    for (int i = 0; i < 4; ++i) {
        int idx = tid + i * 256;
        int row = idx >> 3, u = idx & 7;
        uint32_t so = (uint32_t)(row * G1_ROWB + u * 16);
        CP_ASYNC16(sb + so, (const char*)(d_aggxh + (size_t)(bm + row) * KP1 + u * 8));
        CP_ASYNC16(sb + G1_MAT + so,
                   (const char*)(d_w1t + (size_t)(bn + row) * KP1 + u * 8));
    }
    CP_COMMIT();

    float acc[4][4][4];
#pragma unroll
    for (int i = 0; i < 4; ++i)
#pragma unroll
        for (int j = 0; j < 4; ++j)
#pragma unroll
            for (int q = 0; q < 4; ++q) acc[i][j][q] = 0.f;

    CP_WAIT0();
    __syncthreads();

    const int lr = lane & 7;
    const int lm = lane >> 3;

    uint32_t bf[4][8];
#pragma unroll
    for (int nt = 0; nt < 4; ++nt) {
        uint32_t baddr = sb + G1_MAT +
            (uint32_t)((wn * 32 + nt * 8 + lr) * G1_ROWB + lm * 16);
        LDM_X4(bf[nt][0], bf[nt][1], bf[nt][2], bf[nt][3], baddr);
        LDM_X4(bf[nt][4], bf[nt][5], bf[nt][6], bf[nt][7], baddr + 64);
    }

#pragma unroll
    for (int ks = 0; ks < 4; ++ks) {
        uint32_t af[4][4];
#pragma unroll
        for (int mt = 0; mt < 4; ++mt) {
            uint32_t aaddr = sb +
                (uint32_t)((wm * 64 + mt * 16 + (lm & 1) * 8 + lr) * G1_ROWB +
                           ks * 32 + (lm >> 1) * 16);
            LDM_X4(af[mt][0], af[mt][1], af[mt][2], af[mt][3], aaddr);
        }
#pragma unroll
        for (int mt = 0; mt < 4; ++mt)
#pragma unroll
            for (int nt = 0; nt < 4; ++nt)
                MMA_FP16(acc[mt][nt], af[mt], bf[nt][2 * ks], bf[nt][2 * ks + 1]);
    }

    int r0 = lane >> 2;
    int c0 = (lane & 3) * 2;
#pragma unroll
    for (int nt = 0; nt < 4; ++nt) {
        int gcol = bn + wn * 32 + nt * 8 + c0;
        float b0 = bias[gcol], b1 = bias[gcol + 1];
#pragma unroll
        for (int mt = 0; mt < 4; ++mt) {
            int grow = bm + wm * 64 + mt * 16 + r0;
            *(__half2*)(d_h1h + (size_t)grow * HID1 + gcol) =
                __floats2half2_rn(fmaxf(acc[mt][nt][0] + b0, 0.f),
                                  fmaxf(acc[mt][nt][1] + b1, 0.f));
            *(__half2*)(d_h1h + (size_t)(grow + 8) * HID1 + gcol) =
                __floats2half2_rn(fmaxf(acc[mt][nt][2] + b0, 0.f),
                                  fmaxf(acc[mt][nt][3] + b1, 0.f));
        }
    }
}

// ---------------- GEMM2: block 64x64, 4 warps (warp 32x32), BK=64 -----------
#define G2_ROWB   144
#define G2_AMAT   (64 * G2_ROWB)           // 9216
#define G2_BMAT   (64 * G2_ROWB)           // 9216
#define G2_BUF    (G2_AMAT + G2_BMAT)      // 18432
#define G2_SMEM   (2 * G2_BUF)             // 36864

__global__ void __launch_bounds__(128, 6) k_gemm2_mma() {
    extern __shared__ char smem[];
    uint32_t sb = smem_to_u32(smem);
    const int tid = threadIdx.x;
    const int lane = tid & 31, wid = tid >> 5;
    const int wm = wid >> 1, wn = wid & 1;       // 2(m) x 2(n)
    const int bn = blockIdx.x * 64;
    const int bm = blockIdx.y * 64;

    const int NCHUNK = HID1 / 64;   // 32

    auto fill = [&](int buf, int kt) {
        uint32_t base = sb + buf * G2_BUF;
#pragma unroll
        for (int i = 0; i < 4; ++i) {
            int idx = tid + i * 128;        // 0..511
            int row = idx >> 3;
            int u = idx & 7;
            uint32_t so = (uint32_t)(row * G2_ROWB + u * 16);
            CP_ASYNC16(base + so, (const char*)(d_h1h + (size_t)(bm + row) * HID1 + kt + u * 8));
        }
#pragma unroll
        for (int i = 0; i < 4; ++i) {
            int idx = tid + i * 128;        // 0..511
            int row = idx >> 3;
            int u = idx & 7;
            uint32_t so = (uint32_t)(row * G2_ROWB + u * 16);
            CP_ASYNC16(base + G2_AMAT + so,
                       (const char*)(d_w2t + (size_t)(bn + row) * HID1 + kt + u * 8));
        }
    };

    float acc[2][4][4];
#pragma unroll
    for (int i = 0; i < 2; ++i)
#pragma unroll
        for (int j = 0; j < 4; ++j)
#pragma unroll
            for (int q = 0; q < 4; ++q) acc[i][j][q] = 0.f;

    fill(0, 0);
    CP_COMMIT();
    CP_WAIT0();
    __syncthreads();

    const int lr = lane & 7;
    const int lm = lane >> 3;

    for (int c = 0; c < NCHUNK; ++c) {
        if (c + 1 < NCHUNK) {
            fill((c + 1) & 1, (c + 1) * 64);
            CP_COMMIT();
        }
        uint32_t base = sb + (c & 1) * G2_BUF;

#pragma unroll
        for (int half = 0; half < 2; ++half) {
            uint32_t bf[4][4];
#pragma unroll
            for (int nt = 0; nt < 4; ++nt) {
                uint32_t baddr = base + G2_AMAT +
                    (uint32_t)((wn * 32 + nt * 8 + lr) * G2_ROWB + half * 64 + lm * 16);
                LDM_X4(bf[nt][0], bf[nt][1], bf[nt][2], bf[nt][3], baddr);
            }
#pragma unroll
            for (int ks = 0; ks < 2; ++ks) {
                uint32_t af[2][4];
#pragma unroll
                for (int mt = 0; mt < 2; ++mt) {
                    uint32_t aaddr = base +
                        (uint32_t)((wm * 32 + mt * 16 + (lm & 1) * 8 + lr) * G2_ROWB +
                                   half * 64 + ks * 32 + (lm >> 1) * 16);
                    LDM_X4(af[mt][0], af[mt][1], af[mt][2], af[mt][3], aaddr);
                }
#pragma unroll
                for (int mt = 0; mt < 2; ++mt)
#pragma unroll
                    for (int nt = 0; nt < 4; ++nt)
                        MMA_FP16(acc[mt][nt], af[mt], bf[nt][2 * ks], bf[nt][2 * ks + 1]);
            }
        }
        CP_WAIT0();
        __syncthreads();
    }

    int r0 = lane >> 2;
    int c0 = (lane & 3) * 2;
#pragma unroll
    for (int mt = 0; mt < 2; ++mt) {
#pragma unroll
        for (int nt = 0; nt < 4; ++nt) {
            int grow = bm + wm * 32 + mt * 16 + r0;
            int gcol = bn + wn * 32 + nt * 8 + c0;
            *(__half2*)(d_yh + (size_t)grow * HID2 + gcol) =
                __floats2half2_rn(acc[mt][nt][0], acc[mt][nt][1]);
            *(__half2*)(d_yh + (size_t)(grow + 8) * HID2 + gcol) =
                __floats2half2_rn(acc[mt][nt][2], acc[mt][nt][3]);
        }
    }
}

// ---------------- layer-2 aggregation + bias + relu --------------------------
// 128 threads x uint4 (8 halves each), 2-edge unrolled.
__global__ void k_agg2(const float* __restrict__ b2, int n) {
    int i = blockIdx.x;
    int tid = threadIdx.x;            // 0..127, 8 cols each
    float di = d_dinv[i];
    const uint4* Y = (const uint4*)d_yh;   // 128 uint4 per row
    uint4 raw = Y[(size_t)i * 128 + tid];
    float2 p0 = __half22float2(*(__half2*)&raw.x);
    float2 p1 = __half22float2(*(__half2*)&raw.y);
    float2 p2 = __half22float2(*(__half2*)&raw.z);
    float2 p3 = __half22float2(*(__half2*)&raw.w);
    float c0 = di * di;
    float a0 = p0.x * c0, a1 = p0.y * c0, a2 = p1.x * c0, a3 = p1.y * c0;
    float a4 = p2.x * c0, a5 = p2.y * c0, a6 = p3.x * c0, a7 = p3.y * c0;
    int e0 = d_off[i], e1 = d_off[i + 1];
    int e = e0;
    for (; e + 1 < e1; e += 2) {
        int sA = d_ssrc[e], sB = d_ssrc[e + 1];
        float cA = di * d_dinv[sA];
        float cB = di * d_dinv[sB];
        uint4 uA = Y[(size_t)sA * 128 + tid];
        uint4 uB = Y[(size_t)sB * 128 + tid];
        float2 qa0 = __half22float2(*(__half2*)&uA.x);
        float2 qa1 = __half22float2(*(__half2*)&uA.y);
        float2 qa2 = __half22float2(*(__half2*)&uA.z);
        float2 qa3 = __half22float2(*(__half2*)&uA.w);
        float2 qb0 = __half22float2(*(__half2*)&uB.x);
        float2 qb1 = __half22float2(*(__half2*)&uB.y);
        float2 qb2 = __half22float2(*(__half2*)&uB.z);
        float2 qb3 = __half22float2(*(__half2*)&uB.w);
        a0 += cA * qa0.x + cB * qb0.x;
        a1 += cA * qa0.y + cB * qb0.y;
        a2 += cA * qa1.x + cB * qb1.x;
        a3 += cA * qa1.y + cB * qb1.y;
        a4 += cA * qa2.x + cB * qb2.x;
        a5 += cA * qa2.y + cB * qb2.y;
        a6 += cA * qa3.x + cB * qb3.x;
        a7 += cA * qa3.y + cB * qb3.y;
    }
    if (e < e1) {
        int s = d_ssrc[e];
        float c = di * d_dinv[s];
        uint4 u = Y[(size_t)s * 128 + tid];
        float2 q0 = __half22float2(*(__half2*)&u.x);
        float2 q1 = __half22float2(*(__half2*)&u.y);
        float2 q2 = __half22float2(*(__half2*)&u.z);
        float2 q3 = __half22float2(*(__half2*)&u.w);
        a0 += c * q0.x; a1 += c * q0.y; a2 += c * q1.x; a3 += c * q1.y;
        a4 += c * q2.x; a5 += c * q2.y; a6 += c * q3.x; a7 += c * q3.y;
    }
    const float4* B2 = (const float4*)b2;   // 256 float4 per 1024 cols
    float4 bb0 = B2[tid * 2];
    float4 bb1 = B2[tid * 2 + 1];
    uint4 out;
    *(__half2*)&out.x = __floats2half2_rn(fmaxf(a0 + bb0.x, 0.f), fmaxf(a1 + bb0.y, 0.f));
    *(__half2*)&out.y = __floats2half2_rn(fmaxf(a2 + bb0.z, 0.f), fmaxf(a3 + bb0.w, 0.f));
    *(__half2*)&out.z = __floats2half2_rn(fmaxf(a4 + bb1.x, 0.f), fmaxf(a5 + bb1.y, 0.f));
    *(__half2*)&out.w = __floats2half2_rn(fmaxf(a6 + bb1.z, 0.f), fmaxf(a7 + bb1.w, 0.f));
    ((uint4*)d_x2h)[(size_t)i * 128 + tid] = out;
}

// ---------------- mean pool per graph (2 blocks per graph) -------------------
__global__ void k_pool(const int* __restrict__ batch, int n) {
    int g = blockIdx.x;
    int tid = threadIdx.x;
    int cu = blockIdx.y * 256 + tid;          // u32 index 0..511 (2 cols each)
    int lo = 0, hi = n;
    while (lo < hi) { int m = (lo + hi) >> 1; if (batch[m] < g) lo = m + 1; else hi = m; }
    int s0 = lo;
    hi = n;
    while (lo < hi) { int m = (lo + hi) >> 1; if (batch[m] <= g) lo = m + 1; else hi = m; }
    int s1 = lo;
    float2 acc = make_float2(0.f, 0.f);
    const uint32_t* X = (const uint32_t*)d_x2h;
    for (int i = s0; i < s1; ++i) {
        uint32_t u = X[(size_t)i * 512 + cu];
        float2 q = __half22float2(*(__half2*)&u);
        acc.x += q.x;
        acc.y += q.y;
    }
    int c = s1 - s0;
    float inv = 1.f / (float)(c > 0 ? c : 1);
    *(float2*)(d_pooled + (size_t)g * 1024 + cu * 2) =
        make_float2(acc.x * inv, acc.y * inv);
}

// ---------------- MLP head ----------------------------------------------------
__global__ void k_mlp1(const float* __restrict__ W, const float* __restrict__ bias) {
    __shared__ float sp[1024];
    const int Kd = 1024, Nd = 1024;
    int g = blockIdx.x, cq = blockIdx.y, tid = threadIdx.x;
    for (int k = tid; k < Kd; k += 256) sp[k] = d_pooled[(size_t)g * Kd + k];
    __syncthreads();
    int c = cq * 256 + tid;
    float acc = bias[c];
#pragma unroll 4
    for (int k = 0; k < Kd; ++k)
        acc += sp[k] * W[(size_t)k * Nd + c];
    d_hh1[(size_t)g * Nd + c] = fmaxf(acc, 0.f);
}

// mlp2 fused with output layer
__global__ void k_mlp2_out(const float* __restrict__ W, const float* __restrict__ bias,
                           const float* __restrict__ oW, const float* __restrict__ ob,
                           float* __restrict__ out) {
    __shared__ float sp[1024];
    __shared__ float h2s[512];
    __shared__ float red[512];
    const int Kd = 1024, Nd = 512;
    int g = blockIdx.x, tid = threadIdx.x;
    for (int k = tid; k < Kd; k += 256) sp[k] = d_hh1[(size_t)g * Kd + k];
    __syncthreads();
    int c = tid * 2;
    float a0 = bias[c], a1 = bias[c + 1];
#pragma unroll 4
    for (int k = 0; k < Kd; ++k) {
        float pk = sp[k];
        a0 += pk * W[(size_t)k * Nd + c];
        a1 += pk * W[(size_t)k * Nd + c + 1];
    }
    h2s[c] = fmaxf(a0, 0.f);
    h2s[c + 1] = fmaxf(a1, 0.f);
    __syncthreads();

    float o0 = 0.f, o1 = 0.f;
    for (int k = tid; k < 512; k += 256) {
        float h = h2s[k];
        o0 += h * oW[2 * k];
        o1 += h * oW[2 * k + 1];
    }
    red[tid] = o0;
    red[256 + tid] = o1;
    __syncthreads();
    for (int s = 128; s; s >>= 1) {
        if (tid < s) {
            red[tid] += red[tid + s];
            red[256 + tid] += red[256 + tid + s];
        }
        __syncthreads();
    }
    if (tid == 0) {
        out[g * 2] = red[0] + ob[0];
        out[g * 2 + 1] = red[256] + ob[1];
    }
}

// ---------------- launch ------------------------------------------------------
extern "C" void kernel_launch(void* const* d_in, const int* in_sizes, int n_in,
                              void* d_out, int out_size) {
    const int*   ids   = (const int*)  d_in[0];
    const float* feats = (const float*)d_in[1];
    const int*   eidx  = (const int*)  d_in[2];
    const int*   batch = (const int*)  d_in[3];
    const float* emb   = (const float*)d_in[4];
    const float* W1    = (const float*)d_in[5];
    const float* b1    = (const float*)d_in[6];
    const float* W2    = (const float*)d_in[7];
    const float* b2    = (const float*)d_in[8];
    const float* hW1   = (const float*)d_in[9];
    const float* hb1   = (const float*)d_in[10];
    const float* hW2   = (const float*)d_in[11];
    const float* hb2   = (const float*)d_in[12];
    const float* oW    = (const float*)d_in[13];
    const float* ob    = (const float*)d_in[14];

    int n = in_sizes[0];
    int E = in_sizes[2] / 2;
    int G = out_size / 2;

    const int* src = eidx;
    const int* dst = eidx + E;

    static bool attr_done = false;
    if (!attr_done) {
        cudaFuncSetAttribute(k_gemm2_mma, cudaFuncAttributeMaxDynamicSharedMemorySize,
                             G2_SMEM);
        attr_done = true;
    }

    int nblk = (n + 1023) / 1024;

    k_count<<<(E + 255) / 256, 256>>>(dst, E);
    k_scan1<<<nblk, 1024>>>(n);
    k_scan3<<<nblk, 1024>>>(n, nblk);
    k_scatter<<<(E + 255) / 256, 256>>>(src, dst, E);

    k_prepW1<<<(DIN * HID1) / 256, 256>>>(W1);
    dim3 gp(HID2 / 32, HID1 / 32);
    k_prepB<<<gp, dim3(32, 8)>>>(W2);

    k_agg1<<<(n + 7) / 8, 256>>>(ids, feats, emb, n);

    dim3 g1(HID1 / 128, (n + 127) / 128);
    k_gemm1_mma<<<g1, 256>>>(b1);

    dim3 g2(HID2 / 64, (n + 63) / 64);
    k_gemm2_mma<<<g2, 128, G2_SMEM>>>();

    k_agg2<<<n, 128>>>(b2, n);

    k_pool<<<dim3(G, 2), 256>>>(batch, n);

    k_mlp1<<<dim3(G, 4), 256>>>(hW1, hb1);
    k_mlp2_out<<<G, 256>>>(hW2, hb2, oW, ob, (float*)d_out);
}

// round 17
// speedup vs baseline: 1.1586x; 1.0019x over previous
#include <cuda_runtime.h>
#include <cuda_fp16.h>
#include <stdint.h>

// Problem constants
#define NMAX 20000
#define NPAD 20096
#define EMAX 160000
#define GMAX 64
#define DIN  36
#define KP1  64
#define HID1 2048
#define HID2 1024

// ---------------- scratch (device globals, no runtime alloc) ----------------
__device__ float d_dinv[NMAX];
__device__ int   d_cnt[NMAX];
__device__ int   d_off[NMAX + 1];
__device__ int   d_cur[NMAX];
__device__ int   d_bsum[32];
__device__ int   d_ssrc[EMAX];
__device__ __half d_aggxh[(size_t)NPAD * KP1];   // rows >= n stay zero
__device__ __half d_w1t[(size_t)HID1 * KP1];
__device__ __half d_h1h[(size_t)NPAD * HID1];    // rows >= n stay zero
__device__ __half d_w2t[(size_t)HID2 * HID1];
__device__ __half d_yh[(size_t)NPAD * HID2];     // padded: guard-free epilogue
__device__ __half d_x2h[(size_t)NMAX * HID2];
__device__ float d_pooled[GMAX * HID2];
__device__ float d_hh1[GMAX * 1024];

// ---------------- PTX helpers (base ISA) ------------------------------------
__device__ __forceinline__ uint32_t smem_to_u32(const void* p) {
    uint32_t a;
    asm("{ .reg .u64 t; cvta.to.shared.u64 t, %1; cvt.u32.u64 %0, t; }" : "=r"(a) : "l"(p));
    return a;
}

#define CP_ASYNC16(dst, src) \
    asm volatile("cp.async.cg.shared.global [%0], [%1], 16;" \
        :: "r"(dst), "l"(src) : "memory")
#define CP_COMMIT()  asm volatile("cp.async.commit_group;" ::: "memory")
#define CP_WAIT0()   asm volatile("cp.async.wait_group 0;" ::: "memory")

#define LDM_X4(r0, r1, r2, r3, addr) \
    asm volatile("ldmatrix.sync.aligned.m8n8.x4.shared.b16 {%0,%1,%2,%3}, [%4];" \
        : "=r"(r0), "=r"(r1), "=r"(r2), "=r"(r3) : "r"(addr))

#define MMA_FP16(c, a, b0v, b1v) \
    asm volatile("mma.sync.aligned.m16n8k16.row.col.f32.f16.f16.f32 " \
        "{%0,%1,%2,%3},{%4,%5,%6,%7},{%8,%9},{%0,%1,%2,%3};" \
        : "+f"((c)[0]), "+f"((c)[1]), "+f"((c)[2]), "+f"((c)[3]) \
        : "r"((a)[0]), "r"((a)[1]), "r"((a)[2]), "r"((a)[3]), "r"(b0v), "r"(b1v))

// ---------------- CSR build ----------------
__global__ void k_count(const int* __restrict__ dst, int E) {
    int e = blockIdx.x * blockDim.x + threadIdx.x;
    if (e < E) atomicAdd(&d_cnt[dst[e]], 1);
}

__global__ void k_scan1(int n) {
    __shared__ int wsum[32];
    int tid = threadIdx.x, lane = tid & 31, wrp = tid >> 5;
    int i = blockIdx.x * 1024 + tid;
    int v = (i < n) ? d_cnt[i] : 0;
    int x = v;
#pragma unroll
    for (int s = 1; s < 32; s <<= 1) {
        int t = __shfl_up_sync(0xFFFFFFFF, x, s);
        if (lane >= s) x += t;
    }
    if (lane == 31) wsum[wrp] = x;
    __syncthreads();
    if (wrp == 0) {
        int w = wsum[lane];
#pragma unroll
        for (int s = 1; s < 32; s <<= 1) {
            int t = __shfl_up_sync(0xFFFFFFFF, w, s);
            if (lane >= s) w += t;
        }
        wsum[lane] = w;
    }
    __syncthreads();
    int inc = x + (wrp > 0 ? wsum[wrp - 1] : 0);
    if (i < n) d_off[i] = inc - v;        // block-local exclusive
    if (tid == 1023) d_bsum[blockIdx.x] = inc;   // block total (raw)
}

// stage 2 (fused scan2+scan3): each block sums raw block totals below it.
__global__ void k_scan3(int n, int nblk) {
    __shared__ int base;
    int bid = blockIdx.x;
    if (threadIdx.x == 0) {
        int s = 0;
        for (int j = 0; j < bid; ++j) s += d_bsum[j];
        base = s;
        if (bid == nblk - 1) d_off[n] = s + d_bsum[bid];
    }
    __syncthreads();
    int i = bid * 1024 + threadIdx.x;
    if (i >= n) return;
    int o = d_off[i] + base;
    int c = d_cnt[i];
    d_cnt[i] = 0;                 // self-clean for next replay
    d_off[i] = o;
    d_cur[i] = o;
    d_dinv[i] = rsqrtf((float)(c + 1));
}

__global__ void k_scatter(const int* __restrict__ src, const int* __restrict__ dst, int E) {
    int e = blockIdx.x * blockDim.x + threadIdx.x;
    if (e < E) {
        int d = dst[e];
        int p = atomicAdd(&d_cur[d], 1);
        d_ssrc[p] = src[e];
    }
}

// ---------------- layer-1 aggregation -> fp16 (2-edge unrolled) --------------
__global__ void k_agg1(const int* __restrict__ ids, const float* __restrict__ feats,
                       const float* __restrict__ emb, int n) {
    int w = (blockIdx.x * blockDim.x + threadIdx.x) >> 5;
    int lane = threadIdx.x & 31;
    if (w >= n) return;
    int i = w;
    float di = d_dinv[i];
    float a0 = di * emb[(size_t)ids[i] * 32 + lane];
    float a1 = (lane < 4) ? di * feats[(size_t)i * 4 + lane] : 0.f;
    int e0 = d_off[i], e1 = d_off[i + 1];
    int e = e0;
    for (; e + 1 < e1; e += 2) {
        int sA = d_ssrc[e], sB = d_ssrc[e + 1];
        float cA = d_dinv[sA], cB = d_dinv[sB];
        float vA = emb[(size_t)ids[sA] * 32 + lane];
        float vB = emb[(size_t)ids[sB] * 32 + lane];
        a0 += cA * vA + cB * vB;
        if (lane < 4)
            a1 += cA * feats[(size_t)sA * 4 + lane] + cB * feats[(size_t)sB * 4 + lane];
    }
    if (e < e1) {
        int s = d_ssrc[e];
        float c = d_dinv[s];
        a0 += c * emb[(size_t)ids[s] * 32 + lane];
        if (lane < 4) a1 += c * feats[(size_t)s * 4 + lane];
    }
    d_aggxh[(size_t)i * KP1 + lane] = __float2half_rn(di * a0);
    if (lane < 4) d_aggxh[(size_t)i * KP1 + 32 + lane] = __float2half_rn(di * a1);
}

// ---------------- prep weights ----------------------------------------------
__global__ void k_prepW1(const float* __restrict__ W1) {
    int idx = blockIdx.x * 256 + threadIdx.x;
    int n = idx & (HID1 - 1);
    int k = idx >> 11;
    d_w1t[(size_t)n * KP1 + k] = __float2half_rn(W1[(size_t)k * HID1 + n]);
}

__global__ void k_prepB(const float* __restrict__ W2) {
    __shared__ float t[32][33];
    int nt = blockIdx.x * 32, kt = blockIdx.y * 32;
    int x = threadIdx.x, y = threadIdx.y;
#pragma unroll
    for (int j = 0; j < 4; ++j)
        t[y + j * 8][x] = W2[(size_t)(kt + y + j * 8) * HID2 + nt + x];
    __syncthreads();
#pragma unroll
    for (int j = 0; j < 4; ++j) {
        float v = t[x][y + j * 8];
        d_w2t[(size_t)(nt + y + j * 8) * HID1 + kt + x] = __float2half_rn(v);
    }
}

// ---------------- GEMM1 via mma.sync fp16 (guard-free: NPAD rows) ----------
#define G1_ROWB 144
#define G1_MAT  (128 * G1_ROWB)

__global__ void __launch_bounds__(256) k_gemm1_mma(const float* __restrict__ bias) {
    __shared__ char smem[2 * G1_MAT];
    uint32_t sb = smem_to_u32(smem);
    const int tid = threadIdx.x;
    const int lane = tid & 31, wid = tid >> 5;
    const int wm = wid >> 2, wn = wid & 3;
    const int bn = blockIdx.x * 128;
    const int bm = blockIdx.y * 128;

#pragma unroll
    for (int i = 0; i < 4; ++i) {
        int idx = tid + i * 256;
        int row = idx >> 3, u = idx & 7;
        uint32_t so = (uint32_t)(row * G1_ROWB + u * 16);
        CP_ASYNC16(sb + so, (const char*)(d_aggxh + (size_t)(bm + row) * KP1 + u * 8));
        CP_ASYNC16(sb + G1_MAT + so,
                   (const char*)(d_w1t + (size_t)(bn + row) * KP1 + u * 8));
    }
    CP_COMMIT();

    float acc[4][4][4];
#pragma unroll
    for (int i = 0; i < 4; ++i)
#pragma unroll
        for (int j = 0; j < 4; ++j)
#pragma unroll
            for (int q = 0; q < 4; ++q) acc[i][j][q] = 0.f;

    CP_WAIT0();
    __syncthreads();

    const int lr = lane & 7;
    const int lm = lane >> 3;

    uint32_t bf[4][8];
#pragma unroll
    for (int nt = 0; nt < 4; ++nt) {
        uint32_t baddr = sb + G1_MAT +
            (uint32_t)((wn * 32 + nt * 8 + lr) * G1_ROWB + lm * 16);
        LDM_X4(bf[nt][0], bf[nt][1], bf[nt][2], bf[nt][3], baddr);
        LDM_X4(bf[nt][4], bf[nt][5], bf[nt][6], bf[nt][7], baddr + 64);
    }

#pragma unroll
    for (int ks = 0; ks < 4; ++ks) {
        uint32_t af[4][4];
#pragma unroll
        for (int mt = 0; mt < 4; ++mt) {
            uint32_t aaddr = sb +
                (uint32_t)((wm * 64 + mt * 16 + (lm & 1) * 8 + lr) * G1_ROWB +
                           ks * 32 + (lm >> 1) * 16);
            LDM_X4(af[mt][0], af[mt][1], af[mt][2], af[mt][3], aaddr);
        }
#pragma unroll
        for (int mt = 0; mt < 4; ++mt)
#pragma unroll
            for (int nt = 0; nt < 4; ++nt)
                MMA_FP16(acc[mt][nt], af[mt], bf[nt][2 * ks], bf[nt][2 * ks + 1]);
    }

    int r0 = lane >> 2;
    int c0 = (lane & 3) * 2;
#pragma unroll
    for (int nt = 0; nt < 4; ++nt) {
        int gcol = bn + wn * 32 + nt * 8 + c0;
        float b0 = bias[gcol], b1 = bias[gcol + 1];
#pragma unroll
        for (int mt = 0; mt < 4; ++mt) {
            int grow = bm + wm * 64 + mt * 16 + r0;
            *(__half2*)(d_h1h + (size_t)grow * HID1 + gcol) =
                __floats2half2_rn(fmaxf(acc[mt][nt][0] + b0, 0.f),
                                  fmaxf(acc[mt][nt][1] + b1, 0.f));
            *(__half2*)(d_h1h + (size_t)(grow + 8) * HID1 + gcol) =
                __floats2half2_rn(fmaxf(acc[mt][nt][2] + b0, 0.f),
                                  fmaxf(acc[mt][nt][3] + b1, 0.f));
        }
    }
}

// ---------------- GEMM2: block 64x64, 4 warps (warp 32x32), BK=64 -----------
#define G2_ROWB   144
#define G2_AMAT   (64 * G2_ROWB)           // 9216
#define G2_BMAT   (64 * G2_ROWB)           // 9216
#define G2_BUF    (G2_AMAT + G2_BMAT)      // 18432
#define G2_SMEM   (2 * G2_BUF)             // 36864

__global__ void __launch_bounds__(128, 6) k_gemm2_mma() {
    extern __shared__ char smem[];
    uint32_t sb = smem_to_u32(smem);
    const int tid = threadIdx.x;
    const int lane = tid & 31, wid = tid >> 5;
    const int wm = wid >> 1, wn = wid & 1;       // 2(m) x 2(n)
    const int bn = blockIdx.x * 64;
    const int bm = blockIdx.y * 64;

    const int NCHUNK = HID1 / 64;   // 32

    auto fill = [&](int buf, int kt) {
        uint32_t base = sb + buf * G2_BUF;
#pragma unroll
        for (int i = 0; i < 4; ++i) {
            int idx = tid + i * 128;        // 0..511
            int row = idx >> 3;
            int u = idx & 7;
            uint32_t so = (uint32_t)(row * G2_ROWB + u * 16);
            CP_ASYNC16(base + so, (const char*)(d_h1h + (size_t)(bm + row) * HID1 + kt + u * 8));
        }
#pragma unroll
        for (int i = 0; i < 4; ++i) {
            int idx = tid + i * 128;        // 0..511
            int row = idx >> 3;
            int u = idx & 7;
            uint32_t so = (uint32_t)(row * G2_ROWB + u * 16);
            CP_ASYNC16(base + G2_AMAT + so,
                       (const char*)(d_w2t + (size_t)(bn + row) * HID1 + kt + u * 8));
        }
    };

    float acc[2][4][4];
#pragma unroll
    for (int i = 0; i < 2; ++i)
#pragma unroll
        for (int j = 0; j < 4; ++j)
#pragma unroll
            for (int q = 0; q < 4; ++q) acc[i][j][q] = 0.f;

    fill(0, 0);
    CP_COMMIT();
    CP_WAIT0();
    __syncthreads();

    const int lr = lane & 7;
    const int lm = lane >> 3;

    for (int c = 0; c < NCHUNK; ++c) {
        if (c + 1 < NCHUNK) {
            fill((c + 1) & 1, (c + 1) * 64);
            CP_COMMIT();
        }
        uint32_t base = sb + (c & 1) * G2_BUF;

#pragma unroll
        for (int half = 0; half < 2; ++half) {
            uint32_t bf[4][4];
#pragma unroll
            for (int nt = 0; nt < 4; ++nt) {
                uint32_t baddr = base + G2_AMAT +
                    (uint32_t)((wn * 32 + nt * 8 + lr) * G2_ROWB + half * 64 + lm * 16);
                LDM_X4(bf[nt][0], bf[nt][1], bf[nt][2], bf[nt][3], baddr);
            }
#pragma unroll
            for (int ks = 0; ks < 2; ++ks) {
                uint32_t af[2][4];
#pragma unroll
                for (int mt = 0; mt < 2; ++mt) {
                    uint32_t aaddr = base +
                        (uint32_t)((wm * 32 + mt * 16 + (lm & 1) * 8 + lr) * G2_ROWB +
                                   half * 64 + ks * 32 + (lm >> 1) * 16);
                    LDM_X4(af[mt][0], af[mt][1], af[mt][2], af[mt][3], aaddr);
                }
#pragma unroll
                for (int mt = 0; mt < 2; ++mt)
#pragma unroll
                    for (int nt = 0; nt < 4; ++nt)
                        MMA_FP16(acc[mt][nt], af[mt], bf[nt][2 * ks], bf[nt][2 * ks + 1]);
            }
        }
        CP_WAIT0();
        __syncthreads();
    }

    int r0 = lane >> 2;
    int c0 = (lane & 3) * 2;
#pragma unroll
    for (int mt = 0; mt < 2; ++mt) {
#pragma unroll
        for (int nt = 0; nt < 4; ++nt) {
            int grow = bm + wm * 32 + mt * 16 + r0;
            int gcol = bn + wn * 32 + nt * 8 + c0;
            *(__half2*)(d_yh + (size_t)grow * HID2 + gcol) =
                __floats2half2_rn(acc[mt][nt][0], acc[mt][nt][1]);
            *(__half2*)(d_yh + (size_t)(grow + 8) * HID2 + gcol) =
                __floats2half2_rn(acc[mt][nt][2], acc[mt][nt][3]);
        }
    }
}

// ---------------- layer-2 aggregation + bias + relu --------------------------
// 128 threads x uint4 (8 halves each), 2-edge unrolled.
__global__ void k_agg2(const float* __restrict__ b2, int n) {
    int i = blockIdx.x;
    int tid = threadIdx.x;            // 0..127, 8 cols each
    float di = d_dinv[i];
    const uint4* Y = (const uint4*)d_yh;   // 128 uint4 per row
    uint4 raw = Y[(size_t)i * 128 + tid];
    float2 p0 = __half22float2(*(__half2*)&raw.x);
    float2 p1 = __half22float2(*(__half2*)&raw.y);
    float2 p2 = __half22float2(*(__half2*)&raw.z);
    float2 p3 = __half22float2(*(__half2*)&raw.w);
    float c0 = di * di;
    float a0 = p0.x * c0, a1 = p0.y * c0, a2 = p1.x * c0, a3 = p1.y * c0;
    float a4 = p2.x * c0, a5 = p2.y * c0, a6 = p3.x * c0, a7 = p3.y * c0;
    int e0 = d_off[i], e1 = d_off[i + 1];
    int e = e0;
    for (; e + 1 < e1; e += 2) {
        int sA = d_ssrc[e], sB = d_ssrc[e + 1];
        float cA = di * d_dinv[sA];
        float cB = di * d_dinv[sB];
        uint4 uA = Y[(size_t)sA * 128 + tid];
        uint4 uB = Y[(size_t)sB * 128 + tid];
        float2 qa0 = __half22float2(*(__half2*)&uA.x);
        float2 qa1 = __half22float2(*(__half2*)&uA.y);
        float2 qa2 = __half22float2(*(__half2*)&uA.z);
        float2 qa3 = __half22float2(*(__half2*)&uA.w);
        float2 qb0 = __half22float2(*(__half2*)&uB.x);
        float2 qb1 = __half22float2(*(__half2*)&uB.y);
        float2 qb2 = __half22float2(*(__half2*)&uB.z);
        float2 qb3 = __half22float2(*(__half2*)&uB.w);
        a0 += cA * qa0.x + cB * qb0.x;
        a1 += cA * qa0.y + cB * qb0.y;
        a2 += cA * qa1.x + cB * qb1.x;
        a3 += cA * qa1.y + cB * qb1.y;
        a4 += cA * qa2.x + cB * qb2.x;
        a5 += cA * qa2.y + cB * qb2.y;
        a6 += cA * qa3.x + cB * qb3.x;
        a7 += cA * qa3.y + cB * qb3.y;
    }
    if (e < e1) {
        int s = d_ssrc[e];
        float c = di * d_dinv[s];
        uint4 u = Y[(size_t)s * 128 + tid];
        float2 q0 = __half22float2(*(__half2*)&u.x);
        float2 q1 = __half22float2(*(__half2*)&u.y);
        float2 q2 = __half22float2(*(__half2*)&u.z);
        float2 q3 = __half22float2(*(__half2*)&u.w);
        a0 += c * q0.x; a1 += c * q0.y; a2 += c * q1.x; a3 += c * q1.y;
        a4 += c * q2.x; a5 += c * q2.y; a6 += c * q3.x; a7 += c * q3.y;
    }
    const float4* B2 = (const float4*)b2;   // 256 float4 per 1024 cols
    float4 bb0 = B2[tid * 2];
    float4 bb1 = B2[tid * 2 + 1];
    uint4 out;
    *(__half2*)&out.x = __floats2half2_rn(fmaxf(a0 + bb0.x, 0.f), fmaxf(a1 + bb0.y, 0.f));
    *(__half2*)&out.y = __floats2half2_rn(fmaxf(a2 + bb0.z, 0.f), fmaxf(a3 + bb0.w, 0.f));
    *(__half2*)&out.z = __floats2half2_rn(fmaxf(a4 + bb1.x, 0.f), fmaxf(a5 + bb1.y, 0.f));
    *(__half2*)&out.w = __floats2half2_rn(fmaxf(a6 + bb1.z, 0.f), fmaxf(a7 + bb1.w, 0.f));
    ((uint4*)d_x2h)[(size_t)i * 128 + tid] = out;
}

// ---------------- mean pool per graph (2 blocks per graph) -------------------
__global__ void k_pool(const int* __restrict__ batch, int n) {
    int g = blockIdx.x;
    int tid = threadIdx.x;
    int cu = blockIdx.y * 256 + tid;          // u32 index 0..511 (2 cols each)
    int lo = 0, hi = n;
    while (lo < hi) { int m = (lo + hi) >> 1; if (batch[m] < g) lo = m + 1; else hi = m; }
    int s0 = lo;
    hi = n;
    while (lo < hi) { int m = (lo + hi) >> 1; if (batch[m] <= g) lo = m + 1; else hi = m; }
    int s1 = lo;
    float2 acc = make_float2(0.f, 0.f);
    const uint32_t* X = (const uint32_t*)d_x2h;
    for (int i = s0; i < s1; ++i) {
        uint32_t u = X[(size_t)i * 512 + cu];
        float2 q = __half22float2(*(__half2*)&u);
        acc.x += q.x;
        acc.y += q.y;
    }
    int c = s1 - s0;
    float inv = 1.f / (float)(c > 0 ? c : 1);
    *(float2*)(d_pooled + (size_t)g * 1024 + cu * 2) =
        make_float2(acc.x * inv, acc.y * inv);
}

// ---------------- MLP head ----------------------------------------------------
__global__ void k_mlp1(const float* __restrict__ W, const float* __restrict__ bias) {
    __shared__ float sp[1024];
    const int Kd = 1024, Nd = 1024;
    int g = blockIdx.x, cq = blockIdx.y, tid = threadIdx.x;
    for (int k = tid; k < Kd; k += 256) sp[k] = d_pooled[(size_t)g * Kd + k];
    __syncthreads();
    int c = cq * 256 + tid;
    float acc = bias[c];
#pragma unroll 4
    for (int k = 0; k < Kd; ++k)
        acc += sp[k] * W[(size_t)k * Nd + c];
    d_hh1[(size_t)g * Nd + c] = fmaxf(acc, 0.f);
}

// mlp2 fused with output layer
__global__ void k_mlp2_out(const float* __restrict__ W, const float* __restrict__ bias,
                           const float* __restrict__ oW, const float* __restrict__ ob,
                           float* __restrict__ out) {
    __shared__ float sp[1024];
    __shared__ float h2s[512];
    __shared__ float red[512];
    const int Kd = 1024, Nd = 512;
    int g = blockIdx.x, tid = threadIdx.x;
    for (int k = tid; k < Kd; k += 256) sp[k] = d_hh1[(size_t)g * Kd + k];
    __syncthreads();
    int c = tid * 2;
    float a0 = bias[c], a1 = bias[c + 1];
#pragma unroll 4
    for (int k = 0; k < Kd; ++k) {
        float pk = sp[k];
        a0 += pk * W[(size_t)k * Nd + c];
        a1 += pk * W[(size_t)k * Nd + c + 1];
    }
    h2s[c] = fmaxf(a0, 0.f);
    h2s[c + 1] = fmaxf(a1, 0.f);
    __syncthreads();

    float o0 = 0.f, o1 = 0.f;
    for (int k = tid; k < 512; k += 256) {
        float h = h2s[k];
        o0 += h * oW[2 * k];
        o1 += h * oW[2 * k + 1];
    }
    red[tid] = o0;
    red[256 + tid] = o1;
    __syncthreads();
    for (int s = 128; s; s >>= 1) {
        if (tid < s) {
            red[tid] += red[tid + s];
            red[256 + tid] += red[256 + tid + s];
        }
        __syncthreads();
    }
    if (tid == 0) {
        out[g * 2] = red[0] + ob[0];
        out[g * 2 + 1] = red[256] + ob[1];
    }
}

// ---------------- launch ------------------------------------------------------
extern "C" void kernel_launch(void* const* d_in, const int* in_sizes, int n_in,
                              void* d_out, int out_size) {
    const int*   ids   = (const int*)  d_in[0];
    const float* feats = (const float*)d_in[1];
    const int*   eidx  = (const int*)  d_in[2];
    const int*   batch = (const int*)  d_in[3];
    const float* emb   = (const float*)d_in[4];
    const float* W1    = (const float*)d_in[5];
    const float* b1    = (const float*)d_in[6];
    const float* W2    = (const float*)d_in[7];
    const float* b2    = (const float*)d_in[8];
    const float* hW1   = (const float*)d_in[9];
    const float* hb1   = (const float*)d_in[10];
    const float* hW2   = (const float*)d_in[11];
    const float* hb2   = (const float*)d_in[12];
    const float* oW    = (const float*)d_in[13];
    const float* ob    = (const float*)d_in[14];

    int n = in_sizes[0];
    int E = in_sizes[2] / 2;
    int G = out_size / 2;

    const int* src = eidx;
    const int* dst = eidx + E;

    // one-time setup (first call is the non-captured correctness run)
    static cudaStream_t s2 = 0;
    static cudaEvent_t ev_fork = 0, ev_join = 0;
    static bool init_done = false;
    if (!init_done) {
        cudaFuncSetAttribute(k_gemm2_mma, cudaFuncAttributeMaxDynamicSharedMemorySize,
                             G2_SMEM);
        cudaStreamCreateWithFlags(&s2, cudaStreamNonBlocking);
        cudaEventCreateWithFlags(&ev_fork, cudaEventDisableTiming);
        cudaEventCreateWithFlags(&ev_join, cudaEventDisableTiming);
        init_done = true;
    }

    int nblk = (n + 1023) / 1024;

    // ---- fork: weight preps on s2, overlapping the CSR+agg1 chain ----
    cudaEventRecord(ev_fork, 0);
    cudaStreamWaitEvent(s2, ev_fork, 0);
    k_prepW1<<<(DIN * HID1) / 256, 256, 0, s2>>>(W1);
    {
        dim3 gp(HID2 / 32, HID1 / 32);
        k_prepB<<<gp, dim3(32, 8), 0, s2>>>(W2);
    }
    cudaEventRecord(ev_join, s2);

    // ---- main chain (default stream) ----
    k_count<<<(E + 255) / 256, 256>>>(dst, E);
    k_scan1<<<nblk, 1024>>>(n);
    k_scan3<<<nblk, 1024>>>(n, nblk);
    k_scatter<<<(E + 255) / 256, 256>>>(src, dst, E);

    k_agg1<<<(n + 7) / 8, 256>>>(ids, feats, emb, n);

    // join: GEMM1 needs prepW1 (and GEMM2 needs prepB)
    cudaStreamWaitEvent(0, ev_join, 0);

    dim3 g1(HID1 / 128, (n + 127) / 128);
    k_gemm1_mma<<<g1, 256>>>(b1);

    dim3 g2(HID2 / 64, (n + 63) / 64);
    k_gemm2_mma<<<g2, 128, G2_SMEM>>>();

    k_agg2<<<n, 128>>>(b2, n);

    k_pool<<<dim3(G, 2), 256>>>(batch, n);

    k_mlp1<<<dim3(G, 4), 256>>>(hW1, hb1);
    k_mlp2_out<<<G, 256>>>(hW2, hb2, oW, ob, (float*)d_out);
}